// round 3
// baseline (speedup 1.0000x reference)
#include <cuda_runtime.h>
#include <math.h>

#define HIDDEN 768
#define INTER 3072
#define HEADS 12
#define HEAD_DIM 256
#define BATCH 8
#define SEQ 4096
#define ROWS (BATCH*SEQ)

// ---------------- scratch (static device globals; no allocation) ----------------
__device__ float g_qacc[INTER];            // q pre-scale accumulator (init = bq)
__device__ float g_q[INTER];               // scaled q [h][d]
__device__ float g_wk[HIDDEN*HEADS];       // folded key weights [c][h]
__device__ float g_qbk[HEADS];             // q . bk per head
__device__ float g_logits[BATCH*HEADS*SEQ];
__device__ float g_p[BATCH*HEADS*HIDDEN];  // attn-pooled hidden
__device__ float g_ctx[BATCH*INTER];
__device__ float g_out[BATCH*HIDDEN];      // pre-LN output

// ---------------- K0: init g_p = 0, g_qacc = bq ----------------
__global__ void k0_init(const float* __restrict__ bq) {
    int i = blockIdx.x * 256 + threadIdx.x;        // grid 288*256 = 73728 = |g_p|
    g_p[i] = 0.0f;
    if (i < INTER) g_qacc[i] = bq[i];
}

// ---------------- K1: q partial dots (atomic), grid (12h x 8 cchunk) ----------------
__global__ void k1_qpart(const float* __restrict__ pq, const float* __restrict__ Wq) {
    int h = blockIdx.x >> 3;
    int c0 = (blockIdx.x & 7) * 96;
    __shared__ float sq[96];
    if (threadIdx.x < 96) sq[threadIdx.x] = pq[c0 + threadIdx.x];
    __syncthreads();
    int col = h * HEAD_DIM + threadIdx.x;
    float acc = 0.0f;
#pragma unroll 8
    for (int c = 0; c < 96; c++)
        acc += sq[c] * Wq[(size_t)(c0 + c) * INTER + col];
    atomicAdd(&g_qacc[col], acc);
}

// ---------------- K1b: scale q by scale * softplus(per_dim_scale) ----------------
__global__ void k1b_qscale(const float* __restrict__ pds) {
    int i = blockIdx.x * 256 + threadIdx.x;        // grid 12*256 = 3072
    int d = threadIdx.x;                            // HEAD_DIM == 256
    float x = pds[d];
    float sp = (x > 20.0f) ? x : log1pf(expf(x));
    const float scale = 1.442695041f / 16.0f;       // r_softplus_0 / sqrt(HEAD_DIM)
    g_q[i] = g_qacc[i] * scale * sp;
}

// ---------------- K2: fold wk[c][h] = Wk[c, h*256+d] . q[h,:] ; qbk ----------------
__global__ void k2_fold(const float* __restrict__ Wk, const float* __restrict__ bk) {
    int wid = threadIdx.x >> 5;                     // head (block = 384 = 12 warps)
    int lane = threadIdx.x & 31;
    if (blockIdx.x < HIDDEN) {
        int c = blockIdx.x;
        const float* wrow = Wk + (size_t)c * INTER + wid * HEAD_DIM;
        const float* qrow = g_q + wid * HEAD_DIM;
        float s = 0.0f;
#pragma unroll
        for (int j = lane; j < HEAD_DIM; j += 32) s += wrow[j] * qrow[j];
#pragma unroll
        for (int o = 16; o; o >>= 1) s += __shfl_xor_sync(0xffffffffu, s, o);
        if (!lane) g_wk[c * HEADS + wid] = s;
    } else {                                        // block 768: qbk
        const float* qrow = g_q + wid * HEAD_DIM;
        const float* brow = bk + wid * HEAD_DIM;
        float s = 0.0f;
        for (int j = lane; j < HEAD_DIM; j += 32) s += qrow[j] * brow[j];
#pragma unroll
        for (int o = 16; o; o >>= 1) s += __shfl_xor_sync(0xffffffffu, s, o);
        if (!lane) g_qbk[wid] = s;
    }
}

// ---------------- K3: logits[b,h,s] = hidden row . wk  (big streaming pass A) ----
__global__ __launch_bounds__(256) void k3_logits(const float* __restrict__ hidden) {
    __shared__ float s_wk[HIDDEN * HEADS];          // 36 KB
    __shared__ float s_qbk[HEADS];
    for (int i = threadIdx.x; i < HIDDEN * HEADS; i += 256) s_wk[i] = g_wk[i];
    if (threadIdx.x < HEADS) s_qbk[threadIdx.x] = g_qbk[threadIdx.x];
    __syncthreads();

    int t = blockIdx.x * 256 + threadIdx.x;         // grid 512*256; 4 threads/row
    int row = t >> 2;
    int sub = t & 3;
    const float4* h4 = (const float4*)(hidden + (size_t)row * HIDDEN + sub * 192);

    float acc[HEADS];
#pragma unroll
    for (int h = 0; h < HEADS; h++) acc[h] = 0.0f;

    int cbase = sub * 192;
#pragma unroll 4
    for (int i = 0; i < 48; i++) {
        float4 hv = h4[i];
        const float* w = s_wk + (cbase + i * 4) * HEADS;
        float v0 = hv.x, v1 = hv.y, v2 = hv.z, v3 = hv.w;
#pragma unroll
        for (int h = 0; h < HEADS; h++) acc[h] += v0 * w[h];
#pragma unroll
        for (int h = 0; h < HEADS; h++) acc[h] += v1 * w[HEADS + h];
#pragma unroll
        for (int h = 0; h < HEADS; h++) acc[h] += v2 * w[2 * HEADS + h];
#pragma unroll
        for (int h = 0; h < HEADS; h++) acc[h] += v3 * w[3 * HEADS + h];
    }
#pragma unroll
    for (int h = 0; h < HEADS; h++) {
        acc[h] += __shfl_xor_sync(0xffffffffu, acc[h], 1);
        acc[h] += __shfl_xor_sync(0xffffffffu, acc[h], 2);
    }
    if (sub == 0) {
        int b = row >> 12;
        int s = row & (SEQ - 1);
#pragma unroll
        for (int h = 0; h < HEADS; h++)
            g_logits[((size_t)(b * HEADS + h)) * SEQ + s] = acc[h] + s_qbk[h];
    }
}

// ---------------- K4: softmax over s per (b,h) -> attn output; also init g_ctx/g_out
__global__ __launch_bounds__(256) void k4_softmax(float* __restrict__ out_attn,
                                                  const float* __restrict__ bv,
                                                  const float* __restrict__ bp) {
    int gid = blockIdx.x * 256 + threadIdx.x;       // grid 96*256 = 24576 = |g_ctx|
    g_ctx[gid] = bv[gid % INTER];
    if (gid < BATCH * HIDDEN) g_out[gid] = bp[gid % HIDDEN];

    __shared__ float sv[SEQ];                       // 16 KB
    __shared__ float red[8];
    __shared__ float sbc;
    int bh = blockIdx.x;
    int tid = threadIdx.x, lane = tid & 31, wid = tid >> 5;
    const float* lg = g_logits + (size_t)bh * SEQ;

    float mx = -3.4e38f;
    for (int i = tid; i < SEQ; i += 256) { float v = lg[i]; sv[i] = v; mx = fmaxf(mx, v); }
#pragma unroll
    for (int o = 16; o; o >>= 1) mx = fmaxf(mx, __shfl_xor_sync(0xffffffffu, mx, o));
    if (!lane) red[wid] = mx;
    __syncthreads();
    if (tid == 0) { float m = red[0]; for (int w = 1; w < 8; w++) m = fmaxf(m, red[w]); sbc = m; }
    __syncthreads();
    float m = sbc;

    float sum = 0.0f;
    for (int i = tid; i < SEQ; i += 256) { float e = __expf(sv[i] - m); sv[i] = e; sum += e; }
#pragma unroll
    for (int o = 16; o; o >>= 1) sum += __shfl_xor_sync(0xffffffffu, sum, o);
    if (!lane) red[wid] = sum;
    __syncthreads();
    if (tid == 0) { float s = 0; for (int w = 0; w < 8; w++) s += red[w]; sbc = 1.0f / s; }
    __syncthreads();
    float inv = sbc;
    for (int i = tid; i < SEQ; i += 256) out_attn[(size_t)bh * SEQ + i] = sv[i] * inv;
}

// ---------------- K5: p[b,h,c] = sum_s attn * hidden (big streaming pass C) ------
__global__ __launch_bounds__(192) void k5_pool(const float* __restrict__ hidden,
                                               const float* __restrict__ attn) {
    __shared__ float s_a[64 * HEADS];               // [r][h], 3 KB
    int b = blockIdx.x >> 6;                        // grid = 8*64 blocks, 64 rows each
    int s0 = (blockIdx.x & 63) * 64;
    for (int i = threadIdx.x; i < 64 * HEADS; i += 192) {
        int h = i >> 6, r = i & 63;
        s_a[r * HEADS + h] = attn[((size_t)(b * HEADS + h)) * SEQ + s0 + r];
    }
    __syncthreads();

    int c0 = threadIdx.x * 4;                       // 192*4 = 768
    const float4* hp = (const float4*)(hidden + ((size_t)b * SEQ + s0) * HIDDEN + c0);

    float acc[HEADS * 4];
#pragma unroll
    for (int i = 0; i < HEADS * 4; i++) acc[i] = 0.0f;

#pragma unroll 2
    for (int r = 0; r < 64; r++) {
        float4 hv = hp[(size_t)r * (HIDDEN / 4)];
        const float* ar = s_a + r * HEADS;
#pragma unroll
        for (int h = 0; h < HEADS; h++) {
            float a = ar[h];
            acc[h * 4 + 0] += a * hv.x;
            acc[h * 4 + 1] += a * hv.y;
            acc[h * 4 + 2] += a * hv.z;
            acc[h * 4 + 3] += a * hv.w;
        }
    }
    float* pd = g_p + (size_t)b * HEADS * HIDDEN;
#pragma unroll
    for (int h = 0; h < HEADS; h++)
#pragma unroll
        for (int j = 0; j < 4; j++)
            atomicAdd(&pd[h * HIDDEN + c0 + j], acc[h * 4 + j]);
}

// ---------------- K6a: ctx[b, h*256+d] = p[b,h,:].Wv col + bv (atomic over c) ----
__global__ __launch_bounds__(256) void k6a_ctx(const float* __restrict__ Wv) {
    int h = blockIdx.x >> 4;                        // grid 12*16
    int c0 = (blockIdx.x & 15) * 48;
    __shared__ float sp[BATCH][48];
    for (int i = threadIdx.x; i < BATCH * 48; i += 256) {
        int b = i / 48, c = i % 48;
        sp[b][c] = g_p[(size_t)(b * HEADS + h) * HIDDEN + c0 + c];
    }
    __syncthreads();
    int col = h * HEAD_DIM + threadIdx.x;
    float acc[BATCH];
#pragma unroll
    for (int b = 0; b < BATCH; b++) acc[b] = 0.0f;
#pragma unroll 4
    for (int c = 0; c < 48; c++) {
        float w = Wv[(size_t)(c0 + c) * INTER + col];
#pragma unroll
        for (int b = 0; b < BATCH; b++) acc[b] += sp[b][c] * w;
    }
#pragma unroll
    for (int b = 0; b < BATCH; b++) atomicAdd(&g_ctx[b * INTER + col], acc[b]);
}

// ---------------- K6b: out[b,j] = ctx[b,:].Wp col + bp (atomic over i) -----------
__global__ __launch_bounds__(256) void k6b_out(const float* __restrict__ Wp) {
    int ic = blockIdx.x / 3;                        // grid 48*3
    int jt = blockIdx.x % 3;
    int i0 = ic * 64;
    __shared__ float sc[BATCH][64];
    for (int i = threadIdx.x; i < BATCH * 64; i += 256) {
        int b = i / 64, ii = i % 64;
        sc[b][ii] = g_ctx[b * INTER + i0 + ii];
    }
    __syncthreads();
    int j = jt * 256 + threadIdx.x;
    float acc[BATCH];
#pragma unroll
    for (int b = 0; b < BATCH; b++) acc[b] = 0.0f;
#pragma unroll 4
    for (int ii = 0; ii < 64; ii++) {
        float w = Wp[(size_t)(i0 + ii) * HIDDEN + j];
#pragma unroll
        for (int b = 0; b < BATCH; b++) acc[b] += sc[b][ii] * w;
    }
#pragma unroll
    for (int b = 0; b < BATCH; b++) atomicAdd(&g_out[b * HIDDEN + j], acc[b]);
}

// ---------------- K7: layernorm per batch row -> pooled output -------------------
__global__ __launch_bounds__(256) void k7_ln(float* __restrict__ pooled,
                                             const float* __restrict__ lnw,
                                             const float* __restrict__ lnb) {
    int b = blockIdx.x, tid = threadIdx.x, lane = tid & 31, wid = tid >> 5;
    __shared__ float sx[HIDDEN];
    __shared__ float red[8];
    __shared__ float sm, sr;
    float loc = 0.0f;
    for (int i = tid; i < HIDDEN; i += 256) { float x = g_out[b * HIDDEN + i]; sx[i] = x; loc += x; }
#pragma unroll
    for (int o = 16; o; o >>= 1) loc += __shfl_xor_sync(0xffffffffu, loc, o);
    if (!lane) red[wid] = loc;
    __syncthreads();
    if (tid == 0) { float s = 0; for (int w = 0; w < 8; w++) s += red[w]; sm = s / HIDDEN; }
    __syncthreads();
    float mean = sm;
    loc = 0.0f;
    for (int i = tid; i < HIDDEN; i += 256) { float d = sx[i] - mean; loc += d * d; }
#pragma unroll
    for (int o = 16; o; o >>= 1) loc += __shfl_xor_sync(0xffffffffu, loc, o);
    if (!lane) red[wid] = loc;
    __syncthreads();
    if (tid == 0) { float s = 0; for (int w = 0; w < 8; w++) s += red[w]; sr = rsqrtf(s / HIDDEN + 1e-6f); }
    __syncthreads();
    float rstd = sr;
    for (int i = tid; i < HIDDEN; i += 256)
        pooled[b * HIDDEN + i] = (sx[i] - mean) * rstd * (lnw[i] + 1.0f) + lnb[i];
}

// ---------------- launch -----------------------------------------------------------
extern "C" void kernel_launch(void* const* d_in, const int* in_sizes, int n_in,
                              void* d_out, int out_size) {
    const float* hidden = (const float*)d_in[0];
    const float* pq     = (const float*)d_in[1];
    const float* Wq     = (const float*)d_in[2];
    const float* bq     = (const float*)d_in[3];
    const float* Wk     = (const float*)d_in[4];
    const float* bk     = (const float*)d_in[5];
    const float* Wv     = (const float*)d_in[6];
    const float* bv     = (const float*)d_in[7];
    const float* Wp     = (const float*)d_in[8];
    const float* bp     = (const float*)d_in[9];
    const float* pds    = (const float*)d_in[10];
    const float* lnw    = (const float*)d_in[11];
    const float* lnb    = (const float*)d_in[12];

    float* pooled   = (float*)d_out;                       // [8,1,768]
    float* out_attn = (float*)d_out + BATCH * HIDDEN;      // [8,12,1,4096]

    k0_init   <<<288, 256>>>(bq);
    k1_qpart  <<<96, 256>>>(pq, Wq);
    k1b_qscale<<<12, 256>>>(pds);
    k2_fold   <<<769, 384>>>(Wk, bk);
    k3_logits <<<512, 256>>>(hidden);
    k4_softmax<<<96, 256>>>(out_attn, bv, bp);
    k5_pool   <<<512, 192>>>(hidden, out_attn);
    k6a_ctx   <<<192, 256>>>(Wv);
    k6b_out   <<<144, 256>>>(Wp);
    k7_ln     <<<8, 256>>>(pooled, lnw, lnb);
}

// round 4
// speedup vs baseline: 1.8099x; 1.8099x over previous
#include <cuda_runtime.h>
#include <math.h>

#define HIDDEN 768
#define INTER 3072
#define HEADS 12
#define HEAD_DIM 256
#define BATCH 8
#define SEQ 4096
#define ROWS (BATCH*SEQ)
#define K5_CHUNKS 32
#define K5_ROWS 128

// ---------------- scratch (static device globals; no allocation) ----------------
__device__ float g_qacc[INTER];            // q pre-scale accumulator (init = bq)
__device__ float g_q[INTER];               // scaled q [h][d]
__device__ float g_wk[HIDDEN*HEADS];       // folded key weights [c][h]
__device__ float g_qbk[HEADS];             // q . bk per head
__device__ float g_logits[BATCH*HEADS*SEQ];
__device__ float g_pp[BATCH*K5_CHUNKS*HEADS*HIDDEN]; // pool partials (9.4 MB)
__device__ float g_p[BATCH*HEADS*HIDDEN];  // attn-pooled hidden
__device__ float g_ctx[BATCH*INTER];
__device__ float g_out[BATCH*HIDDEN];      // pre-LN output

// ---------------- K0: g_qacc = bq ----------------
__global__ void k0_init(const float* __restrict__ bq) {
    int i = blockIdx.x * 256 + threadIdx.x;        // grid 12*256 = 3072
    g_qacc[i] = bq[i];
}

// ---------------- K1: q partial dots (atomic), grid (12h x 8 cchunk) -------------
__global__ void k1_qpart(const float* __restrict__ pq, const float* __restrict__ Wq) {
    int h = blockIdx.x >> 3;
    int c0 = (blockIdx.x & 7) * 96;
    __shared__ float sq[96];
    if (threadIdx.x < 96) sq[threadIdx.x] = pq[c0 + threadIdx.x];
    __syncthreads();
    int col = h * HEAD_DIM + threadIdx.x;
    float acc = 0.0f;
#pragma unroll 8
    for (int c = 0; c < 96; c++)
        acc += sq[c] * Wq[(size_t)(c0 + c) * INTER + col];
    atomicAdd(&g_qacc[col], acc);
}

// ---------------- K1b: scale q by scale * softplus(per_dim_scale) ----------------
__global__ void k1b_qscale(const float* __restrict__ pds) {
    int i = blockIdx.x * 256 + threadIdx.x;        // grid 12*256 = 3072
    int d = threadIdx.x;                            // HEAD_DIM == 256
    float x = pds[d];
    float sp = (x > 20.0f) ? x : log1pf(expf(x));
    const float scale = 1.442695041f / 16.0f;       // r_softplus_0 / sqrt(HEAD_DIM)
    g_q[i] = g_qacc[i] * scale * sp;
}

// ---------------- K2: fold wk[c][h] = Wk[c, h*256+:] . q[h,:] ; qbk --------------
// grid 97 blocks x 384 threads (warp == head). Blocks 0..95: 8 c-rows each.
__global__ __launch_bounds__(384) void k2_fold(const float* __restrict__ Wk,
                                               const float* __restrict__ bk) {
    __shared__ float sq[INTER];
    for (int i = threadIdx.x; i < INTER; i += 384) sq[i] = g_q[i];
    __syncthreads();
    int wid = threadIdx.x >> 5;
    int lane = threadIdx.x & 31;
    const float* qh = sq + wid * HEAD_DIM;
    if (blockIdx.x < 96) {
#pragma unroll 2
        for (int cc = 0; cc < 8; cc++) {
            int c = blockIdx.x * 8 + cc;
            const float* wrow = Wk + (size_t)c * INTER + wid * HEAD_DIM;
            float s = 0.0f;
#pragma unroll
            for (int j = 0; j < HEAD_DIM; j += 32) s += wrow[j + lane] * qh[j + lane];
#pragma unroll
            for (int o = 16; o; o >>= 1) s += __shfl_xor_sync(0xffffffffu, s, o);
            if (!lane) g_wk[c * HEADS + wid] = s;
        }
    } else {
        const float* brow = bk + wid * HEAD_DIM;
        float s = 0.0f;
#pragma unroll
        for (int j = 0; j < HEAD_DIM; j += 32) s += qh[j + lane] * brow[j + lane];
#pragma unroll
        for (int o = 16; o; o >>= 1) s += __shfl_xor_sync(0xffffffffu, s, o);
        if (!lane) g_qbk[wid] = s;
    }
}

// ---------------- K3: logits[b,h,s] = hidden row . wk  (big streaming pass A) ----
// One row per thread; weights via conflict-free broadcast LDS.128.
__global__ __launch_bounds__(256) void k3_logits(const float* __restrict__ hidden) {
    __shared__ float s_wk[HIDDEN * HEADS];          // 36 KB, layout [c][h]
    __shared__ float s_qbk[HEADS];
    for (int i = threadIdx.x; i < HIDDEN * HEADS; i += 256) s_wk[i] = g_wk[i];
    if (threadIdx.x < HEADS) s_qbk[threadIdx.x] = g_qbk[threadIdx.x];
    __syncthreads();

    int row = blockIdx.x * 256 + threadIdx.x;       // grid 128 * 256 = 32768 rows
    const float4* h4 = (const float4*)(hidden + (size_t)row * HIDDEN);

    float acc[HEADS];
#pragma unroll
    for (int h = 0; h < HEADS; h++) acc[h] = 0.0f;

#pragma unroll 4
    for (int i = 0; i < HIDDEN / 4; i++) {
        float4 v = h4[i];
        const float4* w4 = (const float4*)(s_wk + i * 4 * HEADS);  // 48 floats = 12 f4
        float vv[4] = {v.x, v.y, v.z, v.w};
#pragma unroll
        for (int j = 0; j < 4; j++) {
            float4 wa = w4[j * 3 + 0];
            float4 wb = w4[j * 3 + 1];
            float4 wc = w4[j * 3 + 2];
            float f = vv[j];
            acc[0] += f * wa.x;  acc[1] += f * wa.y;  acc[2]  += f * wa.z;  acc[3]  += f * wa.w;
            acc[4] += f * wb.x;  acc[5] += f * wb.y;  acc[6]  += f * wb.z;  acc[7]  += f * wb.w;
            acc[8] += f * wc.x;  acc[9] += f * wc.y;  acc[10] += f * wc.z;  acc[11] += f * wc.w;
        }
    }
    int b = row >> 12;
    int s = row & (SEQ - 1);
#pragma unroll
    for (int h = 0; h < HEADS; h++)
        g_logits[((size_t)(b * HEADS + h)) * SEQ + s] = acc[h] + s_qbk[h];
}

// ---------------- K4: softmax over s per (b,h) -> attn output; also init g_ctx/g_out
__global__ __launch_bounds__(256) void k4_softmax(float* __restrict__ out_attn,
                                                  const float* __restrict__ bv,
                                                  const float* __restrict__ bp) {
    int gid = blockIdx.x * 256 + threadIdx.x;       // grid 96*256 = 24576 = |g_ctx|
    g_ctx[gid] = bv[gid % INTER];
    if (gid < BATCH * HIDDEN) g_out[gid] = bp[gid % HIDDEN];

    __shared__ float sv[SEQ];                       // 16 KB
    __shared__ float red[8];
    __shared__ float sbc;
    int bh = blockIdx.x;
    int tid = threadIdx.x, lane = tid & 31, wid = tid >> 5;
    const float* lg = g_logits + (size_t)bh * SEQ;

    float mx = -3.4e38f;
    for (int i = tid; i < SEQ; i += 256) { float v = lg[i]; sv[i] = v; mx = fmaxf(mx, v); }
#pragma unroll
    for (int o = 16; o; o >>= 1) mx = fmaxf(mx, __shfl_xor_sync(0xffffffffu, mx, o));
    if (!lane) red[wid] = mx;
    __syncthreads();
    if (tid == 0) { float m = red[0]; for (int w = 1; w < 8; w++) m = fmaxf(m, red[w]); sbc = m; }
    __syncthreads();
    float m = sbc;

    float sum = 0.0f;
    for (int i = tid; i < SEQ; i += 256) { float e = __expf(sv[i] - m); sv[i] = e; sum += e; }
#pragma unroll
    for (int o = 16; o; o >>= 1) sum += __shfl_xor_sync(0xffffffffu, sum, o);
    if (!lane) red[wid] = sum;
    __syncthreads();
    if (tid == 0) { float s = 0; for (int w = 0; w < 8; w++) s += red[w]; sbc = 1.0f / s; }
    __syncthreads();
    float inv = sbc;
    for (int i = tid; i < SEQ; i += 256) out_attn[(size_t)bh * SEQ + i] = sv[i] * inv;
}

// ---------------- K5: partial p[b,h,c] = sum_s attn * hidden (streaming pass C) --
// grid = 8 b x 32 chunks; 128 rows/chunk; no atomics (per-block partials).
__global__ __launch_bounds__(192) void k5_pool(const float* __restrict__ hidden,
                                               const float* __restrict__ attn) {
    __shared__ float s_a[K5_ROWS * HEADS];          // [r][h], 6 KB, 16B-aligned rows
    int b = blockIdx.x >> 5;
    int s0 = (blockIdx.x & (K5_CHUNKS - 1)) * K5_ROWS;
    for (int i = threadIdx.x; i < K5_ROWS * HEADS; i += 192) {
        int r = i / HEADS, h = i % HEADS;
        s_a[i] = attn[((size_t)(b * HEADS + h)) * SEQ + s0 + r];
    }
    __syncthreads();

    int c0 = threadIdx.x * 4;                       // 192*4 = 768
    const float4* hp = (const float4*)(hidden + ((size_t)b * SEQ + s0) * HIDDEN + c0);

    float4 acc[HEADS];
#pragma unroll
    for (int h = 0; h < HEADS; h++) acc[h] = make_float4(0.f, 0.f, 0.f, 0.f);

#pragma unroll 4
    for (int r = 0; r < K5_ROWS; r++) {
        float4 hv = hp[(size_t)r * (HIDDEN / 4)];
        const float4* ap = (const float4*)(s_a + r * HEADS);  // broadcast, aligned
        float4 a0 = ap[0], a1 = ap[1], a2 = ap[2];
#define K5ACC(hh, av) { acc[hh].x += (av)*hv.x; acc[hh].y += (av)*hv.y; \
                        acc[hh].z += (av)*hv.z; acc[hh].w += (av)*hv.w; }
        K5ACC(0, a0.x)  K5ACC(1, a0.y)  K5ACC(2,  a0.z)  K5ACC(3,  a0.w)
        K5ACC(4, a1.x)  K5ACC(5, a1.y)  K5ACC(6,  a1.z)  K5ACC(7,  a1.w)
        K5ACC(8, a2.x)  K5ACC(9, a2.y)  K5ACC(10, a2.z)  K5ACC(11, a2.w)
#undef K5ACC
    }
    float* pp = g_pp + (size_t)blockIdx.x * (HEADS * HIDDEN);
#pragma unroll
    for (int h = 0; h < HEADS; h++)
        *(float4*)(pp + h * HIDDEN + c0) = acc[h];
}

// ---------------- K5r: reduce chunk partials -> g_p ------------------------------
__global__ __launch_bounds__(256) void k5r_reduce() {
    int i = blockIdx.x * 256 + threadIdx.x;         // grid 288*256 = 73728
    int b = i / (HEADS * HIDDEN);
    int j = i % (HEADS * HIDDEN);
    const float* src = g_pp + (size_t)b * K5_CHUNKS * (HEADS * HIDDEN) + j;
    float s = 0.0f;
#pragma unroll
    for (int ch = 0; ch < K5_CHUNKS; ch++) s += src[(size_t)ch * (HEADS * HIDDEN)];
    g_p[i] = s;
}

// ---------------- K6a: ctx[b, h*256+d] = p[b,h,:].Wv col + bv (atomic over c) ----
__global__ __launch_bounds__(256) void k6a_ctx(const float* __restrict__ Wv) {
    int h = blockIdx.x >> 4;                        // grid 12*16
    int c0 = (blockIdx.x & 15) * 48;
    __shared__ float sp[BATCH][48];
    for (int i = threadIdx.x; i < BATCH * 48; i += 256) {
        int b = i / 48, c = i % 48;
        sp[b][c] = g_p[(size_t)(b * HEADS + h) * HIDDEN + c0 + c];
    }
    __syncthreads();
    int col = h * HEAD_DIM + threadIdx.x;
    float acc[BATCH];
#pragma unroll
    for (int b = 0; b < BATCH; b++) acc[b] = 0.0f;
#pragma unroll 4
    for (int c = 0; c < 48; c++) {
        float w = Wv[(size_t)(c0 + c) * INTER + col];
#pragma unroll
        for (int b = 0; b < BATCH; b++) acc[b] += sp[b][c] * w;
    }
#pragma unroll
    for (int b = 0; b < BATCH; b++) atomicAdd(&g_ctx[b * INTER + col], acc[b]);
}

// ---------------- K6b: out[b,j] = ctx[b,:].Wp col + bp (atomic over i) -----------
__global__ __launch_bounds__(256) void k6b_out(const float* __restrict__ Wp) {
    int ic = blockIdx.x / 3;                        // grid 48*3
    int jt = blockIdx.x % 3;
    int i0 = ic * 64;
    __shared__ float sc[BATCH][64];
    for (int i = threadIdx.x; i < BATCH * 64; i += 256) {
        int b = i / 64, ii = i % 64;
        sc[b][ii] = g_ctx[b * INTER + i0 + ii];
    }
    __syncthreads();
    int j = jt * 256 + threadIdx.x;
    float acc[BATCH];
#pragma unroll
    for (int b = 0; b < BATCH; b++) acc[b] = 0.0f;
#pragma unroll 4
    for (int ii = 0; ii < 64; ii++) {
        float w = Wp[(size_t)(i0 + ii) * HIDDEN + j];
#pragma unroll
        for (int b = 0; b < BATCH; b++) acc[b] += sc[b][ii] * w;
    }
#pragma unroll
    for (int b = 0; b < BATCH; b++) atomicAdd(&g_out[b * HIDDEN + j], acc[b]);
}

// ---------------- K7: layernorm per batch row -> pooled output -------------------
__global__ __launch_bounds__(256) void k7_ln(float* __restrict__ pooled,
                                             const float* __restrict__ lnw,
                                             const float* __restrict__ lnb) {
    int b = blockIdx.x, tid = threadIdx.x, lane = tid & 31, wid = tid >> 5;
    __shared__ float sx[HIDDEN];
    __shared__ float red[8];
    __shared__ float sm, sr;
    float loc = 0.0f;
    for (int i = tid; i < HIDDEN; i += 256) { float x = g_out[b * HIDDEN + i]; sx[i] = x; loc += x; }
#pragma unroll
    for (int o = 16; o; o >>= 1) loc += __shfl_xor_sync(0xffffffffu, loc, o);
    if (!lane) red[wid] = loc;
    __syncthreads();
    if (tid == 0) { float s = 0; for (int w = 0; w < 8; w++) s += red[w]; sm = s / HIDDEN; }
    __syncthreads();
    float mean = sm;
    loc = 0.0f;
    for (int i = tid; i < HIDDEN; i += 256) { float d = sx[i] - mean; loc += d * d; }
#pragma unroll
    for (int o = 16; o; o >>= 1) loc += __shfl_xor_sync(0xffffffffu, loc, o);
    if (!lane) red[wid] = loc;
    __syncthreads();
    if (tid == 0) { float s = 0; for (int w = 0; w < 8; w++) s += red[w]; sr = rsqrtf(s / HIDDEN + 1e-6f); }
    __syncthreads();
    float rstd = sr;
    for (int i = tid; i < HIDDEN; i += 256)
        pooled[b * HIDDEN + i] = (sx[i] - mean) * rstd * (lnw[i] + 1.0f) + lnb[i];
}

// ---------------- launch -----------------------------------------------------------
extern "C" void kernel_launch(void* const* d_in, const int* in_sizes, int n_in,
                              void* d_out, int out_size) {
    const float* hidden = (const float*)d_in[0];
    const float* pq     = (const float*)d_in[1];
    const float* Wq     = (const float*)d_in[2];
    const float* bq     = (const float*)d_in[3];
    const float* Wk     = (const float*)d_in[4];
    const float* bk     = (const float*)d_in[5];
    const float* Wv     = (const float*)d_in[6];
    const float* bv     = (const float*)d_in[7];
    const float* Wp     = (const float*)d_in[8];
    const float* bp     = (const float*)d_in[9];
    const float* pds    = (const float*)d_in[10];
    const float* lnw    = (const float*)d_in[11];
    const float* lnb    = (const float*)d_in[12];

    float* pooled   = (float*)d_out;                       // [8,1,768]
    float* out_attn = (float*)d_out + BATCH * HIDDEN;      // [8,12,1,4096]

    k0_init   <<<12, 256>>>(bq);
    k1_qpart  <<<96, 256>>>(pq, Wq);
    k1b_qscale<<<12, 256>>>(pds);
    k2_fold   <<<97, 384>>>(Wk, bk);
    k3_logits <<<128, 256>>>(hidden);
    k4_softmax<<<96, 256>>>(out_attn, bv, bp);
    k5_pool   <<<256, 192>>>(hidden, out_attn);
    k5r_reduce<<<288, 256>>>();
    k6a_ctx   <<<192, 256>>>(Wv);
    k6b_out   <<<144, 256>>>(Wp);
    k7_ln     <<<8, 256>>>(pooled, lnw, lnb);
}

// round 5
// speedup vs baseline: 1.9612x; 1.0836x over previous
#include <cuda_runtime.h>
#include <math.h>

#define HIDDEN 768
#define INTER 3072
#define HEADS 12
#define HEAD_DIM 256
#define BATCH 8
#define SEQ 4096
#define K5_CHUNKS 32
#define K5_ROWS 128

typedef unsigned long long u64;

// ---------------- f32x2 helpers (sm_103a packed FMA) ----------------
__device__ __forceinline__ u64 pack2(float lo, float hi) {
    u64 r;
    asm("mov.b64 %0, {%1, %2};" : "=l"(r)
        : "r"(__float_as_uint(lo)), "r"(__float_as_uint(hi)));
    return r;
}
__device__ __forceinline__ void fma2(u64& d, u64 a, u64 b) {
    asm("fma.rn.f32x2 %0, %1, %2, %0;" : "+l"(d) : "l"(a), "l"(b));
}
__device__ __forceinline__ float2 unpack2(u64 v) {
    unsigned lo, hi;
    asm("mov.b64 {%0, %1}, %2;" : "=r"(lo), "=r"(hi) : "l"(v));
    return make_float2(__uint_as_float(lo), __uint_as_float(hi));
}

// ---------------- scratch (static device globals; no allocation) ----------------
__device__ float g_q1[24 * INTER];         // q partials per c-chunk
__device__ float g_q[INTER];               // scaled q [h][d]
__device__ float g_wk[HIDDEN * HEADS];     // folded key weights [c][h]
__device__ float g_qbk[HEADS];             // q . bk per head
__device__ float g_logits[BATCH * HEADS * SEQ];
__device__ float g_pp[BATCH * K5_CHUNKS * HEADS * HIDDEN]; // pool partials (9.4 MB)
__device__ float g_p[BATCH * HEADS * HIDDEN];  // attn-pooled hidden
__device__ float g_ctx[BATCH * INTER];
__device__ float g_out[BATCH * HIDDEN];    // pre-LN output

// ---------------- K1: q partials, grid (24 c-chunks x 12 col-chunks) ------------
__global__ __launch_bounds__(256) void k1_qpart(const float* __restrict__ pq,
                                                const float* __restrict__ Wq) {
    int cc = blockIdx.x / 12;                       // 0..23
    int colc = blockIdx.x % 12;                     // 0..11
    int c0 = cc * 32;
    __shared__ float sq[32];
    if (threadIdx.x < 32) sq[threadIdx.x] = pq[c0 + threadIdx.x];
    __syncthreads();
    int col = colc * 256 + threadIdx.x;
    float acc = 0.0f;
#pragma unroll 8
    for (int c = 0; c < 32; c++)
        acc += sq[c] * Wq[(size_t)(c0 + c) * INTER + col];
    g_q1[cc * INTER + col] = acc;
}

// ---------------- K1b: reduce partials + bq, scale by softplus ------------------
__global__ void k1b_qscale(const float* __restrict__ pds,
                           const float* __restrict__ bq) {
    int i = blockIdx.x * 256 + threadIdx.x;         // grid 12*256 = 3072
    float s = bq[i];
#pragma unroll
    for (int cc = 0; cc < 24; cc++) s += g_q1[cc * INTER + i];
    float x = pds[threadIdx.x];                     // HEAD_DIM == 256
    float sp = (x > 20.0f) ? x : log1pf(expf(x));
    const float scale = 1.442695041f / 16.0f;       // r_softplus_0 / sqrt(HEAD_DIM)
    g_q[i] = s * scale * sp;
}

// ---------------- K2: fold wk[c][h] = Wk[c, h*256+:] . q[h,:] ; qbk --------------
// warp-per-(c,h): 9216 dot products + 12 qbk dots. grid 1154 x 256.
__global__ __launch_bounds__(256) void k2_fold(const float* __restrict__ Wk,
                                               const float* __restrict__ bk) {
    int p = blockIdx.x * 8 + (threadIdx.x >> 5);
    int lane = threadIdx.x & 31;
    if (p < HIDDEN * HEADS) {
        int c = p / HEADS;
        int h = p - c * HEADS;
        const float* wrow = Wk + (size_t)c * INTER + h * HEAD_DIM;
        const float* qrow = g_q + h * HEAD_DIM;
        float s = 0.0f;
#pragma unroll
        for (int j = 0; j < HEAD_DIM; j += 32) s += wrow[j + lane] * qrow[j + lane];
#pragma unroll
        for (int o = 16; o; o >>= 1) s += __shfl_xor_sync(0xffffffffu, s, o);
        if (!lane) g_wk[p] = s;
    } else if (p < HIDDEN * HEADS + HEADS) {
        int h = p - HIDDEN * HEADS;
        const float* qrow = g_q + h * HEAD_DIM;
        const float* brow = bk + h * HEAD_DIM;
        float s = 0.0f;
#pragma unroll
        for (int j = 0; j < HEAD_DIM; j += 32) s += qrow[j + lane] * brow[j + lane];
#pragma unroll
        for (int o = 16; o; o >>= 1) s += __shfl_xor_sync(0xffffffffu, s, o);
        if (!lane) g_qbk[h] = s;
    }
}

// ---------------- K3: logits[b,h,s] = hidden row . wk  (streaming pass A) -------
// One row per thread; head-paired f32x2 FMAs; weights via broadcast LDS.128.
__global__ __launch_bounds__(256) void k3_logits(const float* __restrict__ hidden) {
    __shared__ __align__(16) float s_wk[HIDDEN * HEADS]; // 36 KB, [c][h]
    __shared__ float s_qbk[HEADS];
    for (int i = threadIdx.x; i < HIDDEN * HEADS; i += 256) s_wk[i] = g_wk[i];
    if (threadIdx.x < HEADS) s_qbk[threadIdx.x] = g_qbk[threadIdx.x];
    __syncthreads();

    int row = blockIdx.x * 256 + threadIdx.x;       // grid 128 * 256 = 32768 rows
    const float4* h4 = (const float4*)(hidden + (size_t)row * HIDDEN);

    u64 acc[6];                                     // head pairs (0,1)..(10,11)
#pragma unroll
    for (int k = 0; k < 6; k++) acc[k] = 0ull;

#pragma unroll 4
    for (int i = 0; i < HIDDEN / 4; i++) {
        float4 v = h4[i];
        const ulonglong2* w2 = (const ulonglong2*)(s_wk + i * 4 * HEADS);
        float vv[4] = {v.x, v.y, v.z, v.w};
#pragma unroll
        for (int j = 0; j < 4; j++) {
            u64 ff = pack2(vv[j], vv[j]);
            ulonglong2 wa = w2[j * 3 + 0];          // heads 0-3
            ulonglong2 wb = w2[j * 3 + 1];          // heads 4-7
            ulonglong2 wc = w2[j * 3 + 2];          // heads 8-11
            fma2(acc[0], ff, wa.x);
            fma2(acc[1], ff, wa.y);
            fma2(acc[2], ff, wb.x);
            fma2(acc[3], ff, wb.y);
            fma2(acc[4], ff, wc.x);
            fma2(acc[5], ff, wc.y);
        }
    }
    int b = row >> 12;
    int s = row & (SEQ - 1);
#pragma unroll
    for (int k = 0; k < 6; k++) {
        float2 pr = unpack2(acc[k]);
        g_logits[((size_t)(b * HEADS + 2 * k)) * SEQ + s]     = pr.x + s_qbk[2 * k];
        g_logits[((size_t)(b * HEADS + 2 * k + 1)) * SEQ + s] = pr.y + s_qbk[2 * k + 1];
    }
}

// ---------------- K4: softmax over s per (b,h); also init g_ctx/g_out -----------
__global__ __launch_bounds__(256) void k4_softmax(float* __restrict__ out_attn,
                                                  const float* __restrict__ bv,
                                                  const float* __restrict__ bp) {
    int gid = blockIdx.x * 256 + threadIdx.x;       // grid 96*256 = 24576 = |g_ctx|
    g_ctx[gid] = bv[gid % INTER];
    if (gid < BATCH * HIDDEN) g_out[gid] = bp[gid % HIDDEN];

    __shared__ float sv[SEQ];                       // 16 KB
    __shared__ float red[8];
    __shared__ float sbc;
    int bh = blockIdx.x;
    int tid = threadIdx.x, lane = tid & 31, wid = tid >> 5;
    const float* lg = g_logits + (size_t)bh * SEQ;

    float mx = -3.4e38f;
    for (int i = tid; i < SEQ; i += 256) { float v = lg[i]; sv[i] = v; mx = fmaxf(mx, v); }
#pragma unroll
    for (int o = 16; o; o >>= 1) mx = fmaxf(mx, __shfl_xor_sync(0xffffffffu, mx, o));
    if (!lane) red[wid] = mx;
    __syncthreads();
    if (tid == 0) { float m = red[0]; for (int w = 1; w < 8; w++) m = fmaxf(m, red[w]); sbc = m; }
    __syncthreads();
    float m = sbc;

    float sum = 0.0f;
    for (int i = tid; i < SEQ; i += 256) { float e = __expf(sv[i] - m); sv[i] = e; sum += e; }
#pragma unroll
    for (int o = 16; o; o >>= 1) sum += __shfl_xor_sync(0xffffffffu, sum, o);
    if (!lane) red[wid] = sum;
    __syncthreads();
    if (tid == 0) { float s = 0; for (int w = 0; w < 8; w++) s += red[w]; sbc = 1.0f / s; }
    __syncthreads();
    float inv = sbc;
    for (int i = tid; i < SEQ; i += 256) out_attn[(size_t)bh * SEQ + i] = sv[i] * inv;
}

// ---------------- K5: partial p[b,h,c] = sum_s attn * hidden (pass C) -----------
// head-paired f32x2: attn pairs come straight from 16B shared loads.
__global__ __launch_bounds__(192) void k5_pool(const float* __restrict__ hidden,
                                               const float* __restrict__ attn) {
    __shared__ __align__(16) float s_a[K5_ROWS * HEADS]; // [r][h], 6 KB
    int b = blockIdx.x >> 5;
    int s0 = (blockIdx.x & (K5_CHUNKS - 1)) * K5_ROWS;
    for (int i = threadIdx.x; i < K5_ROWS * HEADS; i += 192) {
        int h = i / K5_ROWS, r = i - h * K5_ROWS;   // coalesced attn reads
        s_a[r * HEADS + h] = attn[((size_t)(b * HEADS + h)) * SEQ + s0 + r];
    }
    __syncthreads();

    int c0 = threadIdx.x * 4;                       // 192*4 = 768
    const float4* hp = (const float4*)(hidden + ((size_t)b * SEQ + s0) * HIDDEN + c0);

    u64 acc[6][4];                                  // [head-pair][col]
#pragma unroll
    for (int k = 0; k < 6; k++)
#pragma unroll
        for (int c = 0; c < 4; c++) acc[k][c] = 0ull;

#pragma unroll 4
    for (int r = 0; r < K5_ROWS; r++) {
        float4 hv = hp[(size_t)r * (HIDDEN / 4)];
        u64 hx = pack2(hv.x, hv.x);
        u64 hy = pack2(hv.y, hv.y);
        u64 hz = pack2(hv.z, hv.z);
        u64 hw = pack2(hv.w, hv.w);
        const ulonglong2* ap = (const ulonglong2*)(s_a + r * HEADS);
        ulonglong2 a0 = ap[0], a1 = ap[1], a2 = ap[2];
        u64 av[6] = {a0.x, a0.y, a1.x, a1.y, a2.x, a2.y};
#pragma unroll
        for (int k = 0; k < 6; k++) {
            fma2(acc[k][0], av[k], hx);
            fma2(acc[k][1], av[k], hy);
            fma2(acc[k][2], av[k], hz);
            fma2(acc[k][3], av[k], hw);
        }
    }
    float* pp = g_pp + (size_t)blockIdx.x * (HEADS * HIDDEN);
#pragma unroll
    for (int k = 0; k < 6; k++) {
        float2 p0 = unpack2(acc[k][0]);
        float2 p1 = unpack2(acc[k][1]);
        float2 p2 = unpack2(acc[k][2]);
        float2 p3 = unpack2(acc[k][3]);
        *(float4*)(pp + (2 * k) * HIDDEN + c0)     = make_float4(p0.x, p1.x, p2.x, p3.x);
        *(float4*)(pp + (2 * k + 1) * HIDDEN + c0) = make_float4(p0.y, p1.y, p2.y, p3.y);
    }
}

// ---------------- K5r: reduce chunk partials -> g_p ------------------------------
__global__ __launch_bounds__(256) void k5r_reduce() {
    int i = blockIdx.x * 256 + threadIdx.x;         // grid 288*256 = 73728
    int b = i / (HEADS * HIDDEN);
    int j = i - b * (HEADS * HIDDEN);
    const float* src = g_pp + (size_t)b * K5_CHUNKS * (HEADS * HIDDEN) + j;
    float s = 0.0f;
#pragma unroll
    for (int ch = 0; ch < K5_CHUNKS; ch++) s += src[(size_t)ch * (HEADS * HIDDEN)];
    g_p[i] = s;
}

// ---------------- K6a: ctx[b, h*256+d] = p[b,h,:].Wv col + bv (atomic over c) ----
__global__ __launch_bounds__(256) void k6a_ctx(const float* __restrict__ Wv) {
    int h = blockIdx.x >> 4;                        // grid 12*16
    int c0 = (blockIdx.x & 15) * 48;
    __shared__ float sp[BATCH][48];
    for (int i = threadIdx.x; i < BATCH * 48; i += 256) {
        int b = i / 48, c = i - b * 48;
        sp[b][c] = g_p[(size_t)(b * HEADS + h) * HIDDEN + c0 + c];
    }
    __syncthreads();
    int col = h * HEAD_DIM + threadIdx.x;
    float acc[BATCH];
#pragma unroll
    for (int b = 0; b < BATCH; b++) acc[b] = 0.0f;
#pragma unroll 4
    for (int c = 0; c < 48; c++) {
        float w = Wv[(size_t)(c0 + c) * INTER + col];
#pragma unroll
        for (int b = 0; b < BATCH; b++) acc[b] += sp[b][c] * w;
    }
#pragma unroll
    for (int b = 0; b < BATCH; b++) atomicAdd(&g_ctx[b * INTER + col], acc[b]);
}

// ---------------- K6b: out[b,j] = ctx[b,:].Wp col + bp (atomic over i) -----------
__global__ __launch_bounds__(256) void k6b_out(const float* __restrict__ Wp) {
    int ic = blockIdx.x / 3;                        // grid 48*3
    int jt = blockIdx.x % 3;
    int i0 = ic * 64;
    __shared__ float sc[BATCH][64];
    for (int i = threadIdx.x; i < BATCH * 64; i += 256) {
        int b = i / 64, ii = i - b * 64;
        sc[b][ii] = g_ctx[b * INTER + i0 + ii];
    }
    __syncthreads();
    int j = jt * 256 + threadIdx.x;
    float acc[BATCH];
#pragma unroll
    for (int b = 0; b < BATCH; b++) acc[b] = 0.0f;
#pragma unroll 4
    for (int ii = 0; ii < 64; ii++) {
        float w = Wp[(size_t)(i0 + ii) * HIDDEN + j];
#pragma unroll
        for (int b = 0; b < BATCH; b++) acc[b] += sc[b][ii] * w;
    }
#pragma unroll
    for (int b = 0; b < BATCH; b++) atomicAdd(&g_out[b * HIDDEN + j], acc[b]);
}

// ---------------- K7: layernorm per batch row -> pooled output -------------------
__global__ __launch_bounds__(256) void k7_ln(float* __restrict__ pooled,
                                             const float* __restrict__ lnw,
                                             const float* __restrict__ lnb) {
    int b = blockIdx.x, tid = threadIdx.x, lane = tid & 31, wid = tid >> 5;
    __shared__ float sx[HIDDEN];
    __shared__ float red[8];
    __shared__ float sm, sr;
    float loc = 0.0f;
    for (int i = tid; i < HIDDEN; i += 256) { float x = g_out[b * HIDDEN + i]; sx[i] = x; loc += x; }
#pragma unroll
    for (int o = 16; o; o >>= 1) loc += __shfl_xor_sync(0xffffffffu, loc, o);
    if (!lane) red[wid] = loc;
    __syncthreads();
    if (tid == 0) { float s = 0; for (int w = 0; w < 8; w++) s += red[w]; sm = s / HIDDEN; }
    __syncthreads();
    float mean = sm;
    loc = 0.0f;
    for (int i = tid; i < HIDDEN; i += 256) { float d = sx[i] - mean; loc += d * d; }
#pragma unroll
    for (int o = 16; o; o >>= 1) loc += __shfl_xor_sync(0xffffffffu, loc, o);
    if (!lane) red[wid] = loc;
    __syncthreads();
    if (tid == 0) { float s = 0; for (int w = 0; w < 8; w++) s += red[w]; sr = rsqrtf(s / HIDDEN + 1e-6f); }
    __syncthreads();
    float rstd = sr;
    for (int i = tid; i < HIDDEN; i += 256)
        pooled[b * HIDDEN + i] = (sx[i] - mean) * rstd * (lnw[i] + 1.0f) + lnb[i];
}

// ---------------- launch -----------------------------------------------------------
extern "C" void kernel_launch(void* const* d_in, const int* in_sizes, int n_in,
                              void* d_out, int out_size) {
    const float* hidden = (const float*)d_in[0];
    const float* pq     = (const float*)d_in[1];
    const float* Wq     = (const float*)d_in[2];
    const float* bq     = (const float*)d_in[3];
    const float* Wk     = (const float*)d_in[4];
    const float* bk     = (const float*)d_in[5];
    const float* Wv     = (const float*)d_in[6];
    const float* bv     = (const float*)d_in[7];
    const float* Wp     = (const float*)d_in[8];
    const float* bp     = (const float*)d_in[9];
    const float* pds    = (const float*)d_in[10];
    const float* lnw    = (const float*)d_in[11];
    const float* lnb    = (const float*)d_in[12];

    float* pooled   = (float*)d_out;                       // [8,1,768]
    float* out_attn = (float*)d_out + BATCH * HIDDEN;      // [8,12,1,4096]

    k1_qpart  <<<288, 256>>>(pq, Wq);
    k1b_qscale<<<12, 256>>>(pds, bq);
    k2_fold   <<<1154, 256>>>(Wk, bk);
    k3_logits <<<128, 256>>>(hidden);
    k4_softmax<<<96, 256>>>(out_attn, bv, bp);
    k5_pool   <<<256, 192>>>(hidden, out_attn);
    k5r_reduce<<<288, 256>>>();
    k6a_ctx   <<<192, 256>>>(Wv);
    k6b_out   <<<144, 256>>>(Wp);
    k7_ln     <<<8, 256>>>(pooled, lnw, lnb);
}

// round 6
// speedup vs baseline: 2.0232x; 1.0316x over previous
#include <cuda_runtime.h>
#include <math.h>

#define HIDDEN 768
#define INTER 3072
#define HEADS 12
#define HEAD_DIM 256
#define BATCH 8
#define SEQ 4096
#define K3_CHUNKS 4
#define K3_COLS 192
#define K5_CHUNKS 64
#define K5_ROWS 64

typedef unsigned long long u64;

// ---------------- f32x2 helpers (sm_103a packed FMA) ----------------
__device__ __forceinline__ u64 pack2(float lo, float hi) {
    u64 r;
    asm("mov.b64 %0, {%1, %2};" : "=l"(r)
        : "r"(__float_as_uint(lo)), "r"(__float_as_uint(hi)));
    return r;
}
__device__ __forceinline__ void fma2(u64& d, u64 a, u64 b) {
    asm("fma.rn.f32x2 %0, %1, %2, %0;" : "+l"(d) : "l"(a), "l"(b));
}
__device__ __forceinline__ float2 unpack2(u64 v) {
    unsigned lo, hi;
    asm("mov.b64 {%0, %1}, %2;" : "=r"(lo), "=r"(hi) : "l"(v));
    return make_float2(__uint_as_float(lo), __uint_as_float(hi));
}

// ---------------- scratch (static device globals; no allocation) ----------------
__device__ float g_q1[24 * INTER];         // q partials per c-chunk
__device__ float g_q[INTER];               // scaled q [h][d]
__device__ float g_wk[HIDDEN * HEADS];     // folded key weights [c][h]
__device__ float g_lp[K3_CHUNKS][BATCH * HEADS * SEQ]; // logit partials (6 MB)
__device__ float g_pp[BATCH * K5_CHUNKS * HEADS * HIDDEN]; // pool partials (18.9 MB)
__device__ float g_p[BATCH * HEADS * HIDDEN];  // attn-pooled hidden
__device__ float g_ctx[BATCH * INTER];
__device__ float g_out[BATCH * HIDDEN];    // pre-LN output

// ---------------- K1: q partials, grid (24 c-chunks x 12 col-chunks) ------------
__global__ __launch_bounds__(256) void k1_qpart(const float* __restrict__ pq,
                                                const float* __restrict__ Wq) {
    int cc = blockIdx.x / 12;                       // 0..23
    int colc = blockIdx.x % 12;                     // 0..11
    int c0 = cc * 32;
    __shared__ float sq[32];
    if (threadIdx.x < 32) sq[threadIdx.x] = pq[c0 + threadIdx.x];
    __syncthreads();
    int col = colc * 256 + threadIdx.x;
    float acc = 0.0f;
#pragma unroll 8
    for (int c = 0; c < 32; c++)
        acc += sq[c] * Wq[(size_t)(c0 + c) * INTER + col];
    g_q1[cc * INTER + col] = acc;
}

// ---------------- K1b: reduce partials + bq, scale by softplus ------------------
__global__ void k1b_qscale(const float* __restrict__ pds,
                           const float* __restrict__ bq) {
    int i = blockIdx.x * 256 + threadIdx.x;         // grid 12*256 = 3072
    float s = bq[i];
#pragma unroll
    for (int cc = 0; cc < 24; cc++) s += g_q1[cc * INTER + i];
    float x = pds[threadIdx.x];                     // HEAD_DIM == 256
    float sp = (x > 20.0f) ? x : log1pf(expf(x));
    const float scale = 1.442695041f / 16.0f;       // r_softplus_0 / sqrt(HEAD_DIM)
    g_q[i] = s * scale * sp;
}

// ---------------- K2: fold wk[c][h] = Wk[c, h*256+:] . q[h,:] -------------------
// warp-per-(c,h): 9216 dot products. grid 1152 x 256. (q.bk dropped: softmax-invariant)
__global__ __launch_bounds__(256) void k2_fold(const float* __restrict__ Wk) {
    int p = blockIdx.x * 8 + (threadIdx.x >> 5);
    int lane = threadIdx.x & 31;
    int c = p / HEADS;
    int h = p - c * HEADS;
    const float* wrow = Wk + (size_t)c * INTER + h * HEAD_DIM;
    const float* qrow = g_q + h * HEAD_DIM;
    float s = 0.0f;
#pragma unroll
    for (int j = 0; j < HEAD_DIM; j += 32) s += wrow[j + lane] * qrow[j + lane];
#pragma unroll
    for (int o = 16; o; o >>= 1) s += __shfl_xor_sync(0xffffffffu, s, o);
    if (!lane) g_wk[p] = s;
}

// ---------------- K3: logit partials per col-chunk (streaming pass A) -----------
// grid = 128 rowblocks x 4 chunks = 512; one row per thread, 192 cols per block.
__global__ __launch_bounds__(256) void k3_logits(const float* __restrict__ hidden) {
    __shared__ __align__(16) float s_wk[K3_COLS * HEADS]; // 9 KB, [c][h]
    int chunk = blockIdx.x & 3;
    int rowblk = blockIdx.x >> 2;
    for (int i = threadIdx.x; i < K3_COLS * HEADS; i += 256)
        s_wk[i] = g_wk[chunk * K3_COLS * HEADS + i];
    __syncthreads();

    int row = rowblk * 256 + threadIdx.x;           // 32768 rows
    const float4* h4 = (const float4*)(hidden + (size_t)row * HIDDEN) + chunk * (K3_COLS / 4);

    u64 acc[6];                                     // head pairs (0,1)..(10,11)
#pragma unroll
    for (int k = 0; k < 6; k++) acc[k] = 0ull;

#pragma unroll 4
    for (int i = 0; i < K3_COLS / 4; i++) {
        float4 v = h4[i];
        const ulonglong2* w2 = (const ulonglong2*)(s_wk + i * 4 * HEADS);
        float vv[4] = {v.x, v.y, v.z, v.w};
#pragma unroll
        for (int j = 0; j < 4; j++) {
            u64 ff = pack2(vv[j], vv[j]);
            ulonglong2 wa = w2[j * 3 + 0];
            ulonglong2 wb = w2[j * 3 + 1];
            ulonglong2 wc = w2[j * 3 + 2];
            fma2(acc[0], ff, wa.x);
            fma2(acc[1], ff, wa.y);
            fma2(acc[2], ff, wb.x);
            fma2(acc[3], ff, wb.y);
            fma2(acc[4], ff, wc.x);
            fma2(acc[5], ff, wc.y);
        }
    }
    int b = row >> 12;
    int s = row & (SEQ - 1);
    float* lp = g_lp[chunk];
#pragma unroll
    for (int k = 0; k < 6; k++) {
        float2 pr = unpack2(acc[k]);
        lp[((size_t)(b * HEADS + 2 * k)) * SEQ + s]     = pr.x;
        lp[((size_t)(b * HEADS + 2 * k + 1)) * SEQ + s] = pr.y;
    }
}

// ---------------- K4: sum chunk partials + softmax; also init g_ctx/g_out -------
__global__ __launch_bounds__(256) void k4_softmax(float* __restrict__ out_attn,
                                                  const float* __restrict__ bv,
                                                  const float* __restrict__ bp) {
    int gid = blockIdx.x * 256 + threadIdx.x;       // grid 96*256 = 24576 = |g_ctx|
    g_ctx[gid] = bv[gid % INTER];
    if (gid < BATCH * HIDDEN) g_out[gid] = bp[gid % HIDDEN];

    __shared__ float sv[SEQ];                       // 16 KB
    __shared__ float red[8];
    __shared__ float sbc;
    int bh = blockIdx.x;
    int tid = threadIdx.x, lane = tid & 31, wid = tid >> 5;
    size_t base = (size_t)bh * SEQ;

    float mx = -3.4e38f;
    for (int i = tid; i < SEQ; i += 256) {
        float v = g_lp[0][base + i] + g_lp[1][base + i]
                + g_lp[2][base + i] + g_lp[3][base + i];
        sv[i] = v; mx = fmaxf(mx, v);
    }
#pragma unroll
    for (int o = 16; o; o >>= 1) mx = fmaxf(mx, __shfl_xor_sync(0xffffffffu, mx, o));
    if (!lane) red[wid] = mx;
    __syncthreads();
    if (tid == 0) { float m = red[0]; for (int w = 1; w < 8; w++) m = fmaxf(m, red[w]); sbc = m; }
    __syncthreads();
    float m = sbc;

    float sum = 0.0f;
    for (int i = tid; i < SEQ; i += 256) { float e = __expf(sv[i] - m); sv[i] = e; sum += e; }
#pragma unroll
    for (int o = 16; o; o >>= 1) sum += __shfl_xor_sync(0xffffffffu, sum, o);
    if (!lane) red[wid] = sum;
    __syncthreads();
    if (tid == 0) { float s = 0; for (int w = 0; w < 8; w++) s += red[w]; sbc = 1.0f / s; }
    __syncthreads();
    float inv = sbc;
    for (int i = tid; i < SEQ; i += 256) out_attn[base + i] = sv[i] * inv;
}

// ---------------- K5: partial p[b,h,c] = sum_s attn * hidden (pass C) -----------
// grid = 8 b x 64 chunks = 512; 64 rows/chunk; head-paired f32x2.
__global__ __launch_bounds__(192) void k5_pool(const float* __restrict__ hidden,
                                               const float* __restrict__ attn) {
    __shared__ __align__(16) float s_a[K5_ROWS * HEADS]; // [r][h], 3 KB
    int b = blockIdx.x >> 6;
    int s0 = (blockIdx.x & (K5_CHUNKS - 1)) * K5_ROWS;
    for (int i = threadIdx.x; i < K5_ROWS * HEADS; i += 192) {
        int h = i / K5_ROWS, r = i - h * K5_ROWS;   // coalesced attn reads
        s_a[r * HEADS + h] = attn[((size_t)(b * HEADS + h)) * SEQ + s0 + r];
    }
    __syncthreads();

    int c0 = threadIdx.x * 4;                       // 192*4 = 768
    const float4* hp = (const float4*)(hidden + ((size_t)b * SEQ + s0) * HIDDEN + c0);

    u64 acc[6][4];                                  // [head-pair][col]
#pragma unroll
    for (int k = 0; k < 6; k++)
#pragma unroll
        for (int c = 0; c < 4; c++) acc[k][c] = 0ull;

#pragma unroll 4
    for (int r = 0; r < K5_ROWS; r++) {
        float4 hv = hp[(size_t)r * (HIDDEN / 4)];
        u64 hx = pack2(hv.x, hv.x);
        u64 hy = pack2(hv.y, hv.y);
        u64 hz = pack2(hv.z, hv.z);
        u64 hw = pack2(hv.w, hv.w);
        const ulonglong2* ap = (const ulonglong2*)(s_a + r * HEADS);
        ulonglong2 a0 = ap[0], a1 = ap[1], a2 = ap[2];
        u64 av[6] = {a0.x, a0.y, a1.x, a1.y, a2.x, a2.y};
#pragma unroll
        for (int k = 0; k < 6; k++) {
            fma2(acc[k][0], av[k], hx);
            fma2(acc[k][1], av[k], hy);
            fma2(acc[k][2], av[k], hz);
            fma2(acc[k][3], av[k], hw);
        }
    }
    float* pp = g_pp + (size_t)blockIdx.x * (HEADS * HIDDEN);
#pragma unroll
    for (int k = 0; k < 6; k++) {
        float2 p0 = unpack2(acc[k][0]);
        float2 p1 = unpack2(acc[k][1]);
        float2 p2 = unpack2(acc[k][2]);
        float2 p3 = unpack2(acc[k][3]);
        *(float4*)(pp + (2 * k) * HIDDEN + c0)     = make_float4(p0.x, p1.x, p2.x, p3.x);
        *(float4*)(pp + (2 * k + 1) * HIDDEN + c0) = make_float4(p0.y, p1.y, p2.y, p3.y);
    }
}

// ---------------- K5r: reduce chunk partials -> g_p ------------------------------
__global__ __launch_bounds__(256) void k5r_reduce() {
    int i = blockIdx.x * 256 + threadIdx.x;         // grid 288*256 = 73728
    int b = i / (HEADS * HIDDEN);
    int j = i - b * (HEADS * HIDDEN);
    const float* src = g_pp + (size_t)b * K5_CHUNKS * (HEADS * HIDDEN) + j;
    float s = 0.0f;
#pragma unroll
    for (int ch = 0; ch < K5_CHUNKS; ch++) s += src[(size_t)ch * (HEADS * HIDDEN)];
    g_p[i] = s;
}

// ---------------- K6a: ctx[b, h*256+d] = p[b,h,:].Wv col + bv (atomic over c) ----
__global__ __launch_bounds__(256) void k6a_ctx(const float* __restrict__ Wv) {
    int h = blockIdx.x >> 4;                        // grid 12*16
    int c0 = (blockIdx.x & 15) * 48;
    __shared__ float sp[BATCH][48];
    for (int i = threadIdx.x; i < BATCH * 48; i += 256) {
        int b = i / 48, c = i - b * 48;
        sp[b][c] = g_p[(size_t)(b * HEADS + h) * HIDDEN + c0 + c];
    }
    __syncthreads();
    int col = h * HEAD_DIM + threadIdx.x;
    float acc[BATCH];
#pragma unroll
    for (int b = 0; b < BATCH; b++) acc[b] = 0.0f;
#pragma unroll 4
    for (int c = 0; c < 48; c++) {
        float w = Wv[(size_t)(c0 + c) * INTER + col];
#pragma unroll
        for (int b = 0; b < BATCH; b++) acc[b] += sp[b][c] * w;
    }
#pragma unroll
    for (int b = 0; b < BATCH; b++) atomicAdd(&g_ctx[b * INTER + col], acc[b]);
}

// ---------------- K6b: out[b,j] = ctx[b,:].Wp col + bp (atomic over i) -----------
__global__ __launch_bounds__(256) void k6b_out(const float* __restrict__ Wp) {
    int ic = blockIdx.x / 3;                        // grid 48*3
    int jt = blockIdx.x % 3;
    int i0 = ic * 64;
    __shared__ float sc[BATCH][64];
    for (int i = threadIdx.x; i < BATCH * 64; i += 256) {
        int b = i / 64, ii = i - b * 64;
        sc[b][ii] = g_ctx[b * INTER + i0 + ii];
    }
    __syncthreads();
    int j = jt * 256 + threadIdx.x;
    float acc[BATCH];
#pragma unroll
    for (int b = 0; b < BATCH; b++) acc[b] = 0.0f;
#pragma unroll 4
    for (int ii = 0; ii < 64; ii++) {
        float w = Wp[(size_t)(i0 + ii) * HIDDEN + j];
#pragma unroll
        for (int b = 0; b < BATCH; b++) acc[b] += sc[b][ii] * w;
    }
#pragma unroll
    for (int b = 0; b < BATCH; b++) atomicAdd(&g_out[b * HIDDEN + j], acc[b]);
}

// ---------------- K7: layernorm per batch row -> pooled output -------------------
__global__ __launch_bounds__(256) void k7_ln(float* __restrict__ pooled,
                                             const float* __restrict__ lnw,
                                             const float* __restrict__ lnb) {
    int b = blockIdx.x, tid = threadIdx.x, lane = tid & 31, wid = tid >> 5;
    __shared__ float sx[HIDDEN];
    __shared__ float red[8];
    __shared__ float sm, sr;
    float loc = 0.0f;
    for (int i = tid; i < HIDDEN; i += 256) { float x = g_out[b * HIDDEN + i]; sx[i] = x; loc += x; }
#pragma unroll
    for (int o = 16; o; o >>= 1) loc += __shfl_xor_sync(0xffffffffu, loc, o);
    if (!lane) red[wid] = loc;
    __syncthreads();
    if (tid == 0) { float s = 0; for (int w = 0; w < 8; w++) s += red[w]; sm = s / HIDDEN; }
    __syncthreads();
    float mean = sm;
    loc = 0.0f;
    for (int i = tid; i < HIDDEN; i += 256) { float d = sx[i] - mean; loc += d * d; }
#pragma unroll
    for (int o = 16; o; o >>= 1) loc += __shfl_xor_sync(0xffffffffu, loc, o);
    if (!lane) red[wid] = loc;
    __syncthreads();
    if (tid == 0) { float s = 0; for (int w = 0; w < 8; w++) s += red[w]; sr = rsqrtf(s / HIDDEN + 1e-6f); }
    __syncthreads();
    float rstd = sr;
    for (int i = tid; i < HIDDEN; i += 256)
        pooled[b * HIDDEN + i] = (sx[i] - mean) * rstd * (lnw[i] + 1.0f) + lnb[i];
}

// ---------------- launch -----------------------------------------------------------
extern "C" void kernel_launch(void* const* d_in, const int* in_sizes, int n_in,
                              void* d_out, int out_size) {
    const float* hidden = (const float*)d_in[0];
    const float* pq     = (const float*)d_in[1];
    const float* Wq     = (const float*)d_in[2];
    const float* bq     = (const float*)d_in[3];
    const float* Wk     = (const float*)d_in[4];
    const float* bv     = (const float*)d_in[7];
    const float* Wp     = (const float*)d_in[8];
    const float* bp     = (const float*)d_in[9];
    const float* pds    = (const float*)d_in[10];
    const float* lnw    = (const float*)d_in[11];
    const float* lnb    = (const float*)d_in[12];
    const float* Wv     = (const float*)d_in[6];

    float* pooled   = (float*)d_out;                       // [8,1,768]
    float* out_attn = (float*)d_out + BATCH * HIDDEN;      // [8,12,1,4096]

    k1_qpart  <<<288, 256>>>(pq, Wq);
    k1b_qscale<<<12, 256>>>(pds, bq);
    k2_fold   <<<1152, 256>>>(Wk);
    k3_logits <<<512, 256>>>(hidden);
    k4_softmax<<<96, 256>>>(out_attn, bv, bp);
    k5_pool   <<<512, 192>>>(hidden, out_attn);
    k5r_reduce<<<288, 256>>>();
    k6a_ctx   <<<192, 256>>>(Wv);
    k6b_out   <<<144, 256>>>(Wp);
    k7_ln     <<<8, 256>>>(pooled, lnw, lnb);
}

// round 8
// speedup vs baseline: 2.0640x; 1.0202x over previous
#include <cuda_runtime.h>
#include <math.h>

#define HIDDEN 768
#define INTER 3072
#define HEADS 12
#define HEAD_DIM 256
#define BATCH 8
#define SEQ 4096
#define K3_CHUNKS 4
#define K3_COLS 192
#define K3_TROWS 32
#define K3_PITCH 196          /* 192 + 4 pad; 784B = 49*16B, bank-safe */
#define K5_CHUNKS 64
#define K5_ROWS 64

typedef unsigned long long u64;

// ---------------- f32x2 helpers (sm_103a packed FMA) ----------------
__device__ __forceinline__ u64 pack2(float lo, float hi) {
    u64 r;
    asm("mov.b64 %0, {%1, %2};" : "=l"(r)
        : "r"(__float_as_uint(lo)), "r"(__float_as_uint(hi)));
    return r;
}
__device__ __forceinline__ void fma2(u64& d, u64 a, u64 b) {
    asm("fma.rn.f32x2 %0, %1, %2, %0;" : "+l"(d) : "l"(a), "l"(b));
}
__device__ __forceinline__ float2 unpack2(u64 v) {
    unsigned lo, hi;
    asm("mov.b64 {%0, %1}, %2;" : "=r"(lo), "=r"(hi) : "l"(v));
    return make_float2(__uint_as_float(lo), __uint_as_float(hi));
}

// ---------------- scratch (static device globals; no allocation) ----------------
__device__ float g_q1[24 * INTER];         // q partials per c-chunk
__device__ float g_q[INTER];               // scaled q [h][d]
__device__ float g_wk[HIDDEN * HEADS];     // folded key weights [c][h]
__device__ float g_lp[K3_CHUNKS][BATCH * HEADS * SEQ]; // logit partials (6 MB)
__device__ float g_pp[BATCH * K5_CHUNKS * HEADS * HIDDEN]; // pool partials (18.9 MB)
__device__ float g_p[BATCH * HEADS * HIDDEN];  // attn-pooled hidden
__device__ float g_ctx[BATCH * INTER];
__device__ float g_out[BATCH * HIDDEN];    // pre-LN output

// ---------------- K1: q partials, grid (24 c-chunks x 12 col-chunks) ------------
__global__ __launch_bounds__(256) void k1_qpart(const float* __restrict__ pq,
                                                const float* __restrict__ Wq) {
    int cc = blockIdx.x / 12;                       // 0..23
    int colc = blockIdx.x % 12;                     // 0..11
    int c0 = cc * 32;
    __shared__ float sq[32];
    if (threadIdx.x < 32) sq[threadIdx.x] = pq[c0 + threadIdx.x];
    __syncthreads();
    int col = colc * 256 + threadIdx.x;
    float acc = 0.0f;
#pragma unroll 8
    for (int c = 0; c < 32; c++)
        acc += sq[c] * Wq[(size_t)(c0 + c) * INTER + col];
    g_q1[cc * INTER + col] = acc;
}

// ---------------- K1b: reduce partials + bq, scale by softplus ------------------
__global__ void k1b_qscale(const float* __restrict__ pds,
                           const float* __restrict__ bq) {
    int i = blockIdx.x * 256 + threadIdx.x;         // grid 12*256 = 3072
    float s = bq[i];
#pragma unroll
    for (int cc = 0; cc < 24; cc++) s += g_q1[cc * INTER + i];
    float x = pds[threadIdx.x];                     // HEAD_DIM == 256
    float sp = (x > 20.0f) ? x : log1pf(expf(x));
    const float scale = 1.442695041f / 16.0f;       // r_softplus_0 / sqrt(HEAD_DIM)
    g_q[i] = s * scale * sp;
}

// ---------------- K2: fold wk[c][h] = Wk[c, h*256+:] . q[h,:] -------------------
// warp-per-(c,h): 9216 dot products. grid 1152 x 256. (q.bk dropped: softmax-invariant)
__global__ __launch_bounds__(256) void k2_fold(const float* __restrict__ Wk) {
    int p = blockIdx.x * 8 + (threadIdx.x >> 5);
    int lane = threadIdx.x & 31;
    int c = p / HEADS;
    int h = p - c * HEADS;
    const float* wrow = Wk + (size_t)c * INTER + h * HEAD_DIM;
    const float* qrow = g_q + h * HEAD_DIM;
    float s = 0.0f;
#pragma unroll
    for (int j = 0; j < HEAD_DIM; j += 32) s += wrow[j + lane] * qrow[j + lane];
#pragma unroll
    for (int o = 16; o; o >>= 1) s += __shfl_xor_sync(0xffffffffu, s, o);
    if (!lane) g_wk[p] = s;
}

// ---------------- K3: logit partials; smem-staged coalesced tiles ----------------
// grid = 1024 rowblocks x 4 chunks; block 256; tile = 32 rows x 192 cols.
// Stage: coalesced LDG (4 wavefronts/LDG). Compute: warp w = cols [24w,24w+24),
// lane = row; bank-conflict-free via 196-float pitch. Cross-warp reduce in smem.
__global__ __launch_bounds__(256) void k3_logits(const float* __restrict__ hidden) {
    __shared__ __align__(16) float s_h[K3_TROWS * K3_PITCH];   // 25.1 KB
    __shared__ __align__(16) float s_wk[K3_COLS * HEADS];      // 9 KB
    __shared__ __align__(16) float s_red[8 * K3_TROWS * HEADS];// 12 KB
    int chunk = blockIdx.x & 3;
    int rowblk = blockIdx.x >> 2;
    int row0 = rowblk * K3_TROWS;
    int tid = threadIdx.x;

    for (int i = tid; i < K3_COLS * HEADS; i += 256)
        s_wk[i] = g_wk[chunk * K3_COLS * HEADS + i];

    // stage 32 rows x 192 cols: r = tid>>3, sub = tid&7; 6 float4 each
    {
        int r = tid >> 3, sub = tid & 7;
        const float4* src = (const float4*)(hidden + (size_t)(row0 + r) * HIDDEN
                                            + chunk * K3_COLS);
        float4* dst = (float4*)(s_h + r * K3_PITCH);
#pragma unroll
        for (int j = 0; j < 6; j++)
            dst[sub + 8 * j] = src[sub + 8 * j];
    }
    __syncthreads();

    int w = tid >> 5, lane = tid & 31;              // warp = col group, lane = row
    const float* hrow = s_h + lane * K3_PITCH + w * 24;
    const float* wks = s_wk + (w * 24) * HEADS;

    u64 acc[6];
#pragma unroll
    for (int k = 0; k < 6; k++) acc[k] = 0ull;

#pragma unroll
    for (int i = 0; i < 6; i++) {                   // 6 float4 = 24 cols
        float4 v = *(const float4*)(hrow + 4 * i);
        const ulonglong2* w2 = (const ulonglong2*)(wks + (4 * i) * HEADS);
        float vv[4] = {v.x, v.y, v.z, v.w};
#pragma unroll
        for (int j = 0; j < 4; j++) {
            u64 ff = pack2(vv[j], vv[j]);
            ulonglong2 wa = w2[j * 3 + 0];
            ulonglong2 wb = w2[j * 3 + 1];
            ulonglong2 wc = w2[j * 3 + 2];
            fma2(acc[0], ff, wa.x);
            fma2(acc[1], ff, wa.y);
            fma2(acc[2], ff, wb.x);
            fma2(acc[3], ff, wb.y);
            fma2(acc[4], ff, wc.x);
            fma2(acc[5], ff, wc.y);
        }
    }
    // per-warp partials -> smem
    {
        float* rp = s_red + (w * K3_TROWS + lane) * HEADS;
#pragma unroll
        for (int k = 0; k < 6; k++) {
            float2 pr = unpack2(acc[k]);
            rp[2 * k] = pr.x;
            rp[2 * k + 1] = pr.y;
        }
    }
    __syncthreads();
    // final reduce over 8 warps: 384 outputs (strided — 384 > blockDim!)
    for (int o = tid; o < K3_TROWS * HEADS; o += 256) {
        int rr = o / HEADS, h = o - rr * HEADS;
        float s = 0.0f;
#pragma unroll
        for (int ww = 0; ww < 8; ww++)
            s += s_red[(ww * K3_TROWS + rr) * HEADS + h];
        int grow = row0 + rr;
        int b = grow >> 12;
        int sq = grow & (SEQ - 1);
        g_lp[chunk][((size_t)(b * HEADS + h)) * SEQ + sq] = s;
    }
}

// ---------------- K4: sum chunk partials + softmax; also init g_ctx/g_out -------
__global__ __launch_bounds__(256) void k4_softmax(float* __restrict__ out_attn,
                                                  const float* __restrict__ bv,
                                                  const float* __restrict__ bp) {
    int gid = blockIdx.x * 256 + threadIdx.x;       // grid 96*256 = 24576 = |g_ctx|
    g_ctx[gid] = bv[gid % INTER];
    if (gid < BATCH * HIDDEN) g_out[gid] = bp[gid % HIDDEN];

    __shared__ float sv[SEQ];                       // 16 KB
    __shared__ float red[8];
    __shared__ float sbc;
    int bh = blockIdx.x;
    int tid = threadIdx.x, lane = tid & 31, wid = tid >> 5;
    size_t base = (size_t)bh * SEQ;

    float mx = -3.4e38f;
    for (int i = tid; i < SEQ; i += 256) {
        float v = g_lp[0][base + i] + g_lp[1][base + i]
                + g_lp[2][base + i] + g_lp[3][base + i];
        sv[i] = v; mx = fmaxf(mx, v);
    }
#pragma unroll
    for (int o = 16; o; o >>= 1) mx = fmaxf(mx, __shfl_xor_sync(0xffffffffu, mx, o));
    if (!lane) red[wid] = mx;
    __syncthreads();
    if (tid == 0) { float m = red[0]; for (int w = 1; w < 8; w++) m = fmaxf(m, red[w]); sbc = m; }
    __syncthreads();
    float m = sbc;

    float sum = 0.0f;
    for (int i = tid; i < SEQ; i += 256) { float e = __expf(sv[i] - m); sv[i] = e; sum += e; }
#pragma unroll
    for (int o = 16; o; o >>= 1) sum += __shfl_xor_sync(0xffffffffu, sum, o);
    if (!lane) red[wid] = sum;
    __syncthreads();
    if (tid == 0) { float s = 0; for (int w = 0; w < 8; w++) s += red[w]; sbc = 1.0f / s; }
    __syncthreads();
    float inv = sbc;
    for (int i = tid; i < SEQ; i += 256) out_attn[base + i] = sv[i] * inv;
}

// ---------------- K5: partial p[b,h,c] = sum_s attn * hidden (pass C) -----------
// grid = 8 b x 64 chunks = 512; 64 rows/chunk; head-paired f32x2.
__global__ __launch_bounds__(192) void k5_pool(const float* __restrict__ hidden,
                                               const float* __restrict__ attn) {
    __shared__ __align__(16) float s_a[K5_ROWS * HEADS]; // [r][h], 3 KB
    int b = blockIdx.x >> 6;
    int s0 = (blockIdx.x & (K5_CHUNKS - 1)) * K5_ROWS;
    for (int i = threadIdx.x; i < K5_ROWS * HEADS; i += 192) {
        int h = i / K5_ROWS, r = i - h * K5_ROWS;   // coalesced attn reads
        s_a[r * HEADS + h] = attn[((size_t)(b * HEADS + h)) * SEQ + s0 + r];
    }
    __syncthreads();

    int c0 = threadIdx.x * 4;                       // 192*4 = 768
    const float4* hp = (const float4*)(hidden + ((size_t)b * SEQ + s0) * HIDDEN + c0);

    u64 acc[6][4];                                  // [head-pair][col]
#pragma unroll
    for (int k = 0; k < 6; k++)
#pragma unroll
        for (int c = 0; c < 4; c++) acc[k][c] = 0ull;

#pragma unroll 4
    for (int r = 0; r < K5_ROWS; r++) {
        float4 hv = hp[(size_t)r * (HIDDEN / 4)];
        u64 hx = pack2(hv.x, hv.x);
        u64 hy = pack2(hv.y, hv.y);
        u64 hz = pack2(hv.z, hv.z);
        u64 hw = pack2(hv.w, hv.w);
        const ulonglong2* ap = (const ulonglong2*)(s_a + r * HEADS);
        ulonglong2 a0 = ap[0], a1 = ap[1], a2 = ap[2];
        u64 av[6] = {a0.x, a0.y, a1.x, a1.y, a2.x, a2.y};
#pragma unroll
        for (int k = 0; k < 6; k++) {
            fma2(acc[k][0], av[k], hx);
            fma2(acc[k][1], av[k], hy);
            fma2(acc[k][2], av[k], hz);
            fma2(acc[k][3], av[k], hw);
        }
    }
    float* pp = g_pp + (size_t)blockIdx.x * (HEADS * HIDDEN);
#pragma unroll
    for (int k = 0; k < 6; k++) {
        float2 p0 = unpack2(acc[k][0]);
        float2 p1 = unpack2(acc[k][1]);
        float2 p2 = unpack2(acc[k][2]);
        float2 p3 = unpack2(acc[k][3]);
        *(float4*)(pp + (2 * k) * HIDDEN + c0)     = make_float4(p0.x, p1.x, p2.x, p3.x);
        *(float4*)(pp + (2 * k + 1) * HIDDEN + c0) = make_float4(p0.y, p1.y, p2.y, p3.y);
    }
}

// ---------------- K5r: reduce chunk partials -> g_p ------------------------------
__global__ __launch_bounds__(256) void k5r_reduce() {
    int i = blockIdx.x * 256 + threadIdx.x;         // grid 288*256 = 73728
    int b = i / (HEADS * HIDDEN);
    int j = i - b * (HEADS * HIDDEN);
    const float* src = g_pp + (size_t)b * K5_CHUNKS * (HEADS * HIDDEN) + j;
    float s = 0.0f;
#pragma unroll
    for (int ch = 0; ch < K5_CHUNKS; ch++) s += src[(size_t)ch * (HEADS * HIDDEN)];
    g_p[i] = s;
}

// ---------------- K6a: ctx[b, h*256+d] = p[b,h,:].Wv col + bv (atomic over c) ----
__global__ __launch_bounds__(256) void k6a_ctx(const float* __restrict__ Wv) {
    int h = blockIdx.x >> 4;                        // grid 12*16
    int c0 = (blockIdx.x & 15) * 48;
    __shared__ float sp[BATCH][48];
    for (int i = threadIdx.x; i < BATCH * 48; i += 256) {
        int b = i / 48, c = i - b * 48;
        sp[b][c] = g_p[(size_t)(b * HEADS + h) * HIDDEN + c0 + c];
    }
    __syncthreads();
    int col = h * HEAD_DIM + threadIdx.x;
    float acc[BATCH];
#pragma unroll
    for (int b = 0; b < BATCH; b++) acc[b] = 0.0f;
#pragma unroll 4
    for (int c = 0; c < 48; c++) {
        float w = Wv[(size_t)(c0 + c) * INTER + col];
#pragma unroll
        for (int b = 0; b < BATCH; b++) acc[b] += sp[b][c] * w;
    }
#pragma unroll
    for (int b = 0; b < BATCH; b++) atomicAdd(&g_ctx[b * INTER + col], acc[b]);
}

// ---------------- K6b: out[b,j] = ctx[b,:].Wp col + bp (atomic over i) -----------
__global__ __launch_bounds__(256) void k6b_out(const float* __restrict__ Wp) {
    int ic = blockIdx.x / 3;                        // grid 48*3
    int jt = blockIdx.x % 3;
    int i0 = ic * 64;
    __shared__ float sc[BATCH][64];
    for (int i = threadIdx.x; i < BATCH * 64; i += 256) {
        int b = i / 64, ii = i - b * 64;
        sc[b][ii] = g_ctx[b * INTER + i0 + ii];
    }
    __syncthreads();
    int j = jt * 256 + threadIdx.x;
    float acc[BATCH];
#pragma unroll
    for (int b = 0; b < BATCH; b++) acc[b] = 0.0f;
#pragma unroll 4
    for (int ii = 0; ii < 64; ii++) {
        float w = Wp[(size_t)(i0 + ii) * HIDDEN + j];
#pragma unroll
        for (int b = 0; b < BATCH; b++) acc[b] += sc[b][ii] * w;
    }
#pragma unroll
    for (int b = 0; b < BATCH; b++) atomicAdd(&g_out[b * HIDDEN + j], acc[b]);
}

// ---------------- K7: layernorm per batch row -> pooled output -------------------
__global__ __launch_bounds__(256) void k7_ln(float* __restrict__ pooled,
                                             const float* __restrict__ lnw,
                                             const float* __restrict__ lnb) {
    int b = blockIdx.x, tid = threadIdx.x, lane = tid & 31, wid = tid >> 5;
    __shared__ float sx[HIDDEN];
    __shared__ float red[8];
    __shared__ float sm, sr;
    float loc = 0.0f;
    for (int i = tid; i < HIDDEN; i += 256) { float x = g_out[b * HIDDEN + i]; sx[i] = x; loc += x; }
#pragma unroll
    for (int o = 16; o; o >>= 1) loc += __shfl_xor_sync(0xffffffffu, loc, o);
    if (!lane) red[wid] = loc;
    __syncthreads();
    if (tid == 0) { float s = 0; for (int w = 0; w < 8; w++) s += red[w]; sm = s / HIDDEN; }
    __syncthreads();
    float mean = sm;
    loc = 0.0f;
    for (int i = tid; i < HIDDEN; i += 256) { float d = sx[i] - mean; loc += d * d; }
#pragma unroll
    for (int o = 16; o; o >>= 1) loc += __shfl_xor_sync(0xffffffffu, loc, o);
    if (!lane) red[wid] = loc;
    __syncthreads();
    if (tid == 0) { float s = 0; for (int w = 0; w < 8; w++) s += red[w]; sr = rsqrtf(s / HIDDEN + 1e-6f); }
    __syncthreads();
    float rstd = sr;
    for (int i = tid; i < HIDDEN; i += 256)
        pooled[b * HIDDEN + i] = (sx[i] - mean) * rstd * (lnw[i] + 1.0f) + lnb[i];
}

// ---------------- launch -----------------------------------------------------------
extern "C" void kernel_launch(void* const* d_in, const int* in_sizes, int n_in,
                              void* d_out, int out_size) {
    const float* hidden = (const float*)d_in[0];
    const float* pq     = (const float*)d_in[1];
    const float* Wq     = (const float*)d_in[2];
    const float* bq     = (const float*)d_in[3];
    const float* Wk     = (const float*)d_in[4];
    const float* Wv     = (const float*)d_in[6];
    const float* bv     = (const float*)d_in[7];
    const float* Wp     = (const float*)d_in[8];
    const float* bp     = (const float*)d_in[9];
    const float* pds    = (const float*)d_in[10];
    const float* lnw    = (const float*)d_in[11];
    const float* lnb    = (const float*)d_in[12];

    float* pooled   = (float*)d_out;                       // [8,1,768]
    float* out_attn = (float*)d_out + BATCH * HIDDEN;      // [8,12,1,4096]

    k1_qpart  <<<288, 256>>>(pq, Wq);
    k1b_qscale<<<12, 256>>>(pds, bq);
    k2_fold   <<<1152, 256>>>(Wk);
    k3_logits <<<4096, 256>>>(hidden);
    k4_softmax<<<96, 256>>>(out_attn, bv, bp);
    k5_pool   <<<512, 192>>>(hidden, out_attn);
    k5r_reduce<<<288, 256>>>();
    k6a_ctx   <<<192, 256>>>(Wv);
    k6b_out   <<<144, 256>>>(Wp);
    k7_ln     <<<8, 256>>>(pooled, lnw, lnb);
}

// round 9
// speedup vs baseline: 2.1558x; 1.0445x over previous
#include <cuda_runtime.h>
#include <math.h>

#define HIDDEN 768
#define INTER 3072
#define HEADS 12
#define HEAD_DIM 256
#define BATCH 8
#define SEQ 4096
#define K3_CHUNKS 4
#define K3_COLS 192
#define K3_TROWS 64
#define K3_PITCH 196          /* 192 + 4 pad; 784B stride, bank-safe */
#define K3_SMEM_FLOATS (K3_TROWS * K3_PITCH + K3_COLS * HEADS)
#define K5_CHUNKS 64
#define K5_ROWS 64

typedef unsigned long long u64;

// ---------------- f32x2 helpers (sm_103a packed FMA) ----------------
__device__ __forceinline__ u64 pack2(float lo, float hi) {
    u64 r;
    asm("mov.b64 %0, {%1, %2};" : "=l"(r)
        : "r"(__float_as_uint(lo)), "r"(__float_as_uint(hi)));
    return r;
}
__device__ __forceinline__ void fma2(u64& d, u64 a, u64 b) {
    asm("fma.rn.f32x2 %0, %1, %2, %0;" : "+l"(d) : "l"(a), "l"(b));
}
__device__ __forceinline__ float2 unpack2(u64 v) {
    unsigned lo, hi;
    asm("mov.b64 {%0, %1}, %2;" : "=r"(lo), "=r"(hi) : "l"(v));
    return make_float2(__uint_as_float(lo), __uint_as_float(hi));
}

// ---------------- scratch (static device globals; no allocation) ----------------
__device__ float g_q1[24 * INTER];         // q partials per c-chunk
__device__ float g_q[INTER];               // scaled q [h][d]
__device__ float g_wk[HIDDEN * HEADS];     // folded key weights [c][h]
__device__ float g_lp[K3_CHUNKS][BATCH * HEADS * SEQ]; // logit partials (6 MB)
__device__ float g_pp[BATCH * K5_CHUNKS * HEADS * HIDDEN]; // pool partials (18.9 MB)
__device__ float g_p[BATCH * HEADS * HIDDEN];  // attn-pooled hidden
__device__ float g_ctx[BATCH * INTER];
__device__ float g_out[BATCH * HIDDEN];    // pre-LN output

// ---------------- K1: q partials, grid (24 c-chunks x 12 col-chunks) ------------
__global__ __launch_bounds__(256) void k1_qpart(const float* __restrict__ pq,
                                                const float* __restrict__ Wq) {
    int cc = blockIdx.x / 12;                       // 0..23
    int colc = blockIdx.x % 12;                     // 0..11
    int c0 = cc * 32;
    __shared__ float sq[32];
    if (threadIdx.x < 32) sq[threadIdx.x] = pq[c0 + threadIdx.x];
    __syncthreads();
    int col = colc * 256 + threadIdx.x;
    float acc = 0.0f;
#pragma unroll 8
    for (int c = 0; c < 32; c++)
        acc += sq[c] * Wq[(size_t)(c0 + c) * INTER + col];
    g_q1[cc * INTER + col] = acc;
}

// ---------------- K1b: reduce partials + bq, scale by softplus ------------------
__global__ void k1b_qscale(const float* __restrict__ pds,
                           const float* __restrict__ bq) {
    int i = blockIdx.x * 256 + threadIdx.x;         // grid 12*256 = 3072
    float s = bq[i];
#pragma unroll
    for (int cc = 0; cc < 24; cc++) s += g_q1[cc * INTER + i];
    float x = pds[threadIdx.x];                     // HEAD_DIM == 256
    float sp = (x > 20.0f) ? x : log1pf(expf(x));
    const float scale = 1.442695041f / 16.0f;       // r_softplus_0 / sqrt(HEAD_DIM)
    g_q[i] = s * scale * sp;
}

// ---------------- K2: fold wk[c][h] = Wk[c, h*256+:] . q[h,:] -------------------
// warp-per-(c,h): 9216 dot products. grid 1152 x 256. (q.bk dropped: softmax-invariant)
__global__ __launch_bounds__(256) void k2_fold(const float* __restrict__ Wk) {
    int p = blockIdx.x * 8 + (threadIdx.x >> 5);
    int lane = threadIdx.x & 31;
    int c = p / HEADS;
    int h = p - c * HEADS;
    const float* wrow = Wk + (size_t)c * INTER + h * HEAD_DIM;
    const float* qrow = g_q + h * HEAD_DIM;
    float s = 0.0f;
#pragma unroll
    for (int j = 0; j < HEAD_DIM; j += 32) s += wrow[j + lane] * qrow[j + lane];
#pragma unroll
    for (int o = 16; o; o >>= 1) s += __shfl_xor_sync(0xffffffffu, s, o);
    if (!lane) g_wk[p] = s;
}

// ---------------- K3: logit partials; 64-row tiles, weight-LDS amortized --------
// grid = 512 rowblocks x 4 chunks = 2048; block 256; dynamic smem 58 KB.
// Stage 64 rows x 192 cols (coalesced). Warp w = cols [24w,24w+24); lane handles
// rows lane and lane+32 -> each weight LDS feeds 12 FMA2. s_red aliases s_h.
__global__ __launch_bounds__(256) void k3_logits(const float* __restrict__ hidden) {
    extern __shared__ __align__(16) float dsm[];
    float* s_h  = dsm;                               // 64*196 = 12544 floats
    float* s_wk = dsm + K3_TROWS * K3_PITCH;         // 192*12 = 2304 floats
    float* s_red = dsm;                              // aliased after compute (6144)
    int chunk = blockIdx.x & 3;
    int rowblk = blockIdx.x >> 2;
    int row0 = rowblk * K3_TROWS;
    int tid = threadIdx.x;

    for (int i = tid; i < K3_COLS * HEADS; i += 256)
        s_wk[i] = g_wk[chunk * K3_COLS * HEADS + i];

    // stage 64 rows x 192 cols: r = tid>>2, sub = tid&3; 12 float4 each
    {
        int r = tid >> 2, sub = tid & 3;
        const float4* src = (const float4*)(hidden + (size_t)(row0 + r) * HIDDEN
                                            + chunk * K3_COLS);
        float4* dst = (float4*)(s_h + r * K3_PITCH);
#pragma unroll
        for (int j = 0; j < 12; j++)
            dst[sub + 4 * j] = src[sub + 4 * j];
    }
    __syncthreads();

    int w = tid >> 5, lane = tid & 31;
    const float* h0 = s_h + lane * K3_PITCH + w * 24;
    const float* h1 = h0 + 32 * K3_PITCH;
    const float* wks = s_wk + (w * 24) * HEADS;

    u64 acc0[6], acc1[6];
#pragma unroll
    for (int k = 0; k < 6; k++) { acc0[k] = 0ull; acc1[k] = 0ull; }

#pragma unroll
    for (int i = 0; i < 6; i++) {                   // 6 float4 = 24 cols
        float4 va = *(const float4*)(h0 + 4 * i);
        float4 vb = *(const float4*)(h1 + 4 * i);
        const ulonglong2* w2 = (const ulonglong2*)(wks + (4 * i) * HEADS);
        float aa[4] = {va.x, va.y, va.z, va.w};
        float bb[4] = {vb.x, vb.y, vb.z, vb.w};
#pragma unroll
        for (int j = 0; j < 4; j++) {
            ulonglong2 wa = w2[j * 3 + 0];
            ulonglong2 wb = w2[j * 3 + 1];
            ulonglong2 wc = w2[j * 3 + 2];
            u64 fa = pack2(aa[j], aa[j]);
            u64 fb = pack2(bb[j], bb[j]);
            fma2(acc0[0], fa, wa.x);
            fma2(acc0[1], fa, wa.y);
            fma2(acc0[2], fa, wb.x);
            fma2(acc0[3], fa, wb.y);
            fma2(acc0[4], fa, wc.x);
            fma2(acc0[5], fa, wc.y);
            fma2(acc1[0], fb, wa.x);
            fma2(acc1[1], fb, wa.y);
            fma2(acc1[2], fb, wb.x);
            fma2(acc1[3], fb, wb.y);
            fma2(acc1[4], fb, wc.x);
            fma2(acc1[5], fb, wc.y);
        }
    }
    __syncthreads();                                // all s_h reads done (aliasing)
    // per-warp partials -> s_red [w][row][head]
    {
        float* rp0 = s_red + (w * K3_TROWS + lane) * HEADS;
        float* rp1 = s_red + (w * K3_TROWS + lane + 32) * HEADS;
#pragma unroll
        for (int k = 0; k < 6; k++) {
            float2 p0 = unpack2(acc0[k]);
            float2 p1 = unpack2(acc1[k]);
            rp0[2 * k] = p0.x; rp0[2 * k + 1] = p0.y;
            rp1[2 * k] = p1.x; rp1[2 * k + 1] = p1.y;
        }
    }
    __syncthreads();
    // final reduce over 8 warps: 768 outputs, strided
    for (int o = tid; o < K3_TROWS * HEADS; o += 256) {
        int rr = o / HEADS, h = o - rr * HEADS;
        float s = 0.0f;
#pragma unroll
        for (int ww = 0; ww < 8; ww++)
            s += s_red[(ww * K3_TROWS + rr) * HEADS + h];
        int grow = row0 + rr;
        int b = grow >> 12;
        int sq = grow & (SEQ - 1);
        g_lp[chunk][((size_t)(b * HEADS + h)) * SEQ + sq] = s;
    }
}

// ---------------- K4: sum chunk partials + softmax; also init g_ctx/g_out -------
__global__ __launch_bounds__(256) void k4_softmax(float* __restrict__ out_attn,
                                                  const float* __restrict__ bv,
                                                  const float* __restrict__ bp) {
    int gid = blockIdx.x * 256 + threadIdx.x;       // grid 96*256 = 24576 = |g_ctx|
    g_ctx[gid] = bv[gid % INTER];
    if (gid < BATCH * HIDDEN) g_out[gid] = bp[gid % HIDDEN];

    __shared__ float sv[SEQ];                       // 16 KB
    __shared__ float red[8];
    __shared__ float sbc;
    int bh = blockIdx.x;
    int tid = threadIdx.x, lane = tid & 31, wid = tid >> 5;
    size_t base = (size_t)bh * SEQ;

    float mx = -3.4e38f;
    for (int i = tid; i < SEQ; i += 256) {
        float v = g_lp[0][base + i] + g_lp[1][base + i]
                + g_lp[2][base + i] + g_lp[3][base + i];
        sv[i] = v; mx = fmaxf(mx, v);
    }
#pragma unroll
    for (int o = 16; o; o >>= 1) mx = fmaxf(mx, __shfl_xor_sync(0xffffffffu, mx, o));
    if (!lane) red[wid] = mx;
    __syncthreads();
    if (tid == 0) { float m = red[0]; for (int w = 1; w < 8; w++) m = fmaxf(m, red[w]); sbc = m; }
    __syncthreads();
    float m = sbc;

    float sum = 0.0f;
    for (int i = tid; i < SEQ; i += 256) { float e = __expf(sv[i] - m); sv[i] = e; sum += e; }
#pragma unroll
    for (int o = 16; o; o >>= 1) sum += __shfl_xor_sync(0xffffffffu, sum, o);
    if (!lane) red[wid] = sum;
    __syncthreads();
    if (tid == 0) { float s = 0; for (int w = 0; w < 8; w++) s += red[w]; sbc = 1.0f / s; }
    __syncthreads();
    float inv = sbc;
    for (int i = tid; i < SEQ; i += 256) out_attn[base + i] = sv[i] * inv;
}

// ---------------- K5: partial p[b,h,c] = sum_s attn * hidden (pass C) -----------
// grid = 8 b x 64 chunks = 512; 64 rows/chunk; head-paired f32x2.
__global__ __launch_bounds__(192) void k5_pool(const float* __restrict__ hidden,
                                               const float* __restrict__ attn) {
    __shared__ __align__(16) float s_a[K5_ROWS * HEADS]; // [r][h], 3 KB
    int b = blockIdx.x >> 6;
    int s0 = (blockIdx.x & (K5_CHUNKS - 1)) * K5_ROWS;
    for (int i = threadIdx.x; i < K5_ROWS * HEADS; i += 192) {
        int h = i / K5_ROWS, r = i - h * K5_ROWS;   // coalesced attn reads
        s_a[r * HEADS + h] = attn[((size_t)(b * HEADS + h)) * SEQ + s0 + r];
    }
    __syncthreads();

    int c0 = threadIdx.x * 4;                       // 192*4 = 768
    const float4* hp = (const float4*)(hidden + ((size_t)b * SEQ + s0) * HIDDEN + c0);

    u64 acc[6][4];                                  // [head-pair][col]
#pragma unroll
    for (int k = 0; k < 6; k++)
#pragma unroll
        for (int c = 0; c < 4; c++) acc[k][c] = 0ull;

#pragma unroll 4
    for (int r = 0; r < K5_ROWS; r++) {
        float4 hv = hp[(size_t)r * (HIDDEN / 4)];
        u64 hx = pack2(hv.x, hv.x);
        u64 hy = pack2(hv.y, hv.y);
        u64 hz = pack2(hv.z, hv.z);
        u64 hw = pack2(hv.w, hv.w);
        const ulonglong2* ap = (const ulonglong2*)(s_a + r * HEADS);
        ulonglong2 a0 = ap[0], a1 = ap[1], a2 = ap[2];
        u64 av[6] = {a0.x, a0.y, a1.x, a1.y, a2.x, a2.y};
#pragma unroll
        for (int k = 0; k < 6; k++) {
            fma2(acc[k][0], av[k], hx);
            fma2(acc[k][1], av[k], hy);
            fma2(acc[k][2], av[k], hz);
            fma2(acc[k][3], av[k], hw);
        }
    }
    float* pp = g_pp + (size_t)blockIdx.x * (HEADS * HIDDEN);
#pragma unroll
    for (int k = 0; k < 6; k++) {
        float2 p0 = unpack2(acc[k][0]);
        float2 p1 = unpack2(acc[k][1]);
        float2 p2 = unpack2(acc[k][2]);
        float2 p3 = unpack2(acc[k][3]);
        *(float4*)(pp + (2 * k) * HIDDEN + c0)     = make_float4(p0.x, p1.x, p2.x, p3.x);
        *(float4*)(pp + (2 * k + 1) * HIDDEN + c0) = make_float4(p0.y, p1.y, p2.y, p3.y);
    }
}

// ---------------- K5r: reduce chunk partials -> g_p ------------------------------
__global__ __launch_bounds__(256) void k5r_reduce() {
    int i = blockIdx.x * 256 + threadIdx.x;         // grid 288*256 = 73728
    int b = i / (HEADS * HIDDEN);
    int j = i - b * (HEADS * HIDDEN);
    const float* src = g_pp + (size_t)b * K5_CHUNKS * (HEADS * HIDDEN) + j;
    float s = 0.0f;
#pragma unroll
    for (int ch = 0; ch < K5_CHUNKS; ch++) s += src[(size_t)ch * (HEADS * HIDDEN)];
    g_p[i] = s;
}

// ---------------- K6a: ctx[b, h*256+d] = p[b,h,:].Wv col + bv (atomic over c) ----
__global__ __launch_bounds__(256) void k6a_ctx(const float* __restrict__ Wv) {
    int h = blockIdx.x >> 4;                        // grid 12*16
    int c0 = (blockIdx.x & 15) * 48;
    __shared__ float sp[BATCH][48];
    for (int i = threadIdx.x; i < BATCH * 48; i += 256) {
        int b = i / 48, c = i - b * 48;
        sp[b][c] = g_p[(size_t)(b * HEADS + h) * HIDDEN + c0 + c];
    }
    __syncthreads();
    int col = h * HEAD_DIM + threadIdx.x;
    float acc[BATCH];
#pragma unroll
    for (int b = 0; b < BATCH; b++) acc[b] = 0.0f;
#pragma unroll 4
    for (int c = 0; c < 48; c++) {
        float w = Wv[(size_t)(c0 + c) * INTER + col];
#pragma unroll
        for (int b = 0; b < BATCH; b++) acc[b] += sp[b][c] * w;
    }
#pragma unroll
    for (int b = 0; b < BATCH; b++) atomicAdd(&g_ctx[b * INTER + col], acc[b]);
}

// ---------------- K6b: out[b,j] = ctx[b,:].Wp col + bp (atomic over i) -----------
__global__ __launch_bounds__(256) void k6b_out(const float* __restrict__ Wp) {
    int ic = blockIdx.x / 3;                        // grid 48*3
    int jt = blockIdx.x % 3;
    int i0 = ic * 64;
    __shared__ float sc[BATCH][64];
    for (int i = threadIdx.x; i < BATCH * 64; i += 256) {
        int b = i / 64, ii = i - b * 64;
        sc[b][ii] = g_ctx[b * INTER + i0 + ii];
    }
    __syncthreads();
    int j = jt * 256 + threadIdx.x;
    float acc[BATCH];
#pragma unroll
    for (int b = 0; b < BATCH; b++) acc[b] = 0.0f;
#pragma unroll 4
    for (int ii = 0; ii < 64; ii++) {
        float w = Wp[(size_t)(i0 + ii) * HIDDEN + j];
#pragma unroll
        for (int b = 0; b < BATCH; b++) acc[b] += sc[b][ii] * w;
    }
#pragma unroll
    for (int b = 0; b < BATCH; b++) atomicAdd(&g_out[b * HIDDEN + j], acc[b]);
}

// ---------------- K7: layernorm per batch row -> pooled output -------------------
__global__ __launch_bounds__(256) void k7_ln(float* __restrict__ pooled,
                                             const float* __restrict__ lnw,
                                             const float* __restrict__ lnb) {
    int b = blockIdx.x, tid = threadIdx.x, lane = tid & 31, wid = tid >> 5;
    __shared__ float sx[HIDDEN];
    __shared__ float red[8];
    __shared__ float sm, sr;
    float loc = 0.0f;
    for (int i = tid; i < HIDDEN; i += 256) { float x = g_out[b * HIDDEN + i]; sx[i] = x; loc += x; }
#pragma unroll
    for (int o = 16; o; o >>= 1) loc += __shfl_xor_sync(0xffffffffu, loc, o);
    if (!lane) red[wid] = loc;
    __syncthreads();
    if (tid == 0) { float s = 0; for (int w = 0; w < 8; w++) s += red[w]; sm = s / HIDDEN; }
    __syncthreads();
    float mean = sm;
    loc = 0.0f;
    for (int i = tid; i < HIDDEN; i += 256) { float d = sx[i] - mean; loc += d * d; }
#pragma unroll
    for (int o = 16; o; o >>= 1) loc += __shfl_xor_sync(0xffffffffu, loc, o);
    if (!lane) red[wid] = loc;
    __syncthreads();
    if (tid == 0) { float s = 0; for (int w = 0; w < 8; w++) s += red[w]; sr = rsqrtf(s / HIDDEN + 1e-6f); }
    __syncthreads();
    float rstd = sr;
    for (int i = tid; i < HIDDEN; i += 256)
        pooled[b * HIDDEN + i] = (sx[i] - mean) * rstd * (lnw[i] + 1.0f) + lnb[i];
}

// ---------------- launch -----------------------------------------------------------
extern "C" void kernel_launch(void* const* d_in, const int* in_sizes, int n_in,
                              void* d_out, int out_size) {
    const float* hidden = (const float*)d_in[0];
    const float* pq     = (const float*)d_in[1];
    const float* Wq     = (const float*)d_in[2];
    const float* bq     = (const float*)d_in[3];
    const float* Wk     = (const float*)d_in[4];
    const float* Wv     = (const float*)d_in[6];
    const float* bv     = (const float*)d_in[7];
    const float* Wp     = (const float*)d_in[8];
    const float* bp     = (const float*)d_in[9];
    const float* pds    = (const float*)d_in[10];
    const float* lnw    = (const float*)d_in[11];
    const float* lnb    = (const float*)d_in[12];

    float* pooled   = (float*)d_out;                       // [8,1,768]
    float* out_attn = (float*)d_out + BATCH * HIDDEN;      // [8,12,1,4096]

    const int k3_smem = K3_SMEM_FLOATS * sizeof(float);    // 59392 B
    static int s_attr_done = 0;
    if (!s_attr_done) {
        cudaFuncSetAttribute(k3_logits, cudaFuncAttributeMaxDynamicSharedMemorySize,
                             k3_smem);
        s_attr_done = 1;
    }

    k1_qpart  <<<288, 256>>>(pq, Wq);
    k1b_qscale<<<12, 256>>>(pds, bq);
    k2_fold   <<<1152, 256>>>(Wk);
    k3_logits <<<2048, 256, k3_smem>>>(hidden);
    k4_softmax<<<96, 256>>>(out_attn, bv, bp);
    k5_pool   <<<512, 192>>>(hidden, out_attn);
    k5r_reduce<<<288, 256>>>();
    k6a_ctx   <<<192, 256>>>(Wv);
    k6b_out   <<<144, 256>>>(Wp);
    k7_ln     <<<8, 256>>>(pooled, lnw, lnb);
}